// round 5
// baseline (speedup 1.0000x reference)
#include <cuda_runtime.h>
#include <math.h>

#define NB 4
#define NT 4096
#define NC 512
#define NH 64
#define NM (NB*NT)            // 16384 rows

// scratch for k, q, v projections: [3][B*T][H]
__device__ float g_kqv[3][(size_t)NM * NH];

// ---------------------------------------------------------------------------
// Kernel 1: fused QKV projection (unchanged from R3 — near SIMT floor).
// ---------------------------------------------------------------------------
__global__ __launch_bounds__(256) void proj_kernel(
    const float* __restrict__ x,
    const float* __restrict__ Wk,
    const float* __restrict__ Wq,
    const float* __restrict__ Wv)
{
    __shared__ float As[64 * 32];
    __shared__ float Bs[32 * 64];

    const int tid = threadIdx.x;
    const int ty  = tid >> 4;
    const int tx  = tid & 15;
    const int m0  = blockIdx.x * 64;
    const int w   = blockIdx.y;
    const float* __restrict__ W = (w == 0) ? Wk : (w == 1) ? Wq : Wv;

    float acc[4][4];
#pragma unroll
    for (int i = 0; i < 4; i++)
#pragma unroll
        for (int j = 0; j < 4; j++) acc[i][j] = 0.f;

    for (int k0 = 0; k0 < NC; k0 += 32) {
#pragma unroll
        for (int u = 0; u < 2; u++) {
            int f = tid + u * 256;
            int r = f >> 3, c = f & 7;
            *(float4*)&As[r * 32 + c * 4] =
                *(const float4*)&x[(size_t)(m0 + r) * NC + k0 + c * 4];
        }
#pragma unroll
        for (int u = 0; u < 2; u++) {
            int f = tid + u * 256;
            int r = f >> 4, c = f & 15;
            *(float4*)&Bs[r * 64 + c * 4] =
                *(const float4*)&W[(size_t)(k0 + r) * NH + c * 4];
        }
        __syncthreads();

#pragma unroll
        for (int kk = 0; kk < 32; kk += 4) {
            float av[4][4], bv[4][4];
#pragma unroll
            for (int i = 0; i < 4; i++) {
                float4 t4 = *(float4*)&As[(ty * 4 + i) * 32 + kk];
                av[i][0] = t4.x; av[i][1] = t4.y; av[i][2] = t4.z; av[i][3] = t4.w;
            }
#pragma unroll
            for (int t = 0; t < 4; t++) {
                float4 t4 = *(float4*)&Bs[(kk + t) * 64 + tx * 4];
                bv[t][0] = t4.x; bv[t][1] = t4.y; bv[t][2] = t4.z; bv[t][3] = t4.w;
            }
#pragma unroll
            for (int i = 0; i < 4; i++)
#pragma unroll
                for (int j = 0; j < 4; j++)
#pragma unroll
                    for (int t = 0; t < 4; t++)
                        acc[i][j] = fmaf(av[i][t], bv[t][j], acc[i][j]);
        }
        __syncthreads();
    }

    const float scale = (w == 1) ? 0.044194173824159216f : 1.0f;
    float* __restrict__ outb = g_kqv[w];
#pragma unroll
    for (int i = 0; i < 4; i++) {
        float4 o4 = make_float4(acc[i][0] * scale, acc[i][1] * scale,
                                acc[i][2] * scale, acc[i][3] * scale);
        *(float4*)&outb[(size_t)(m0 + ty * 4 + i) * NH + tx * 4] = o4;
    }
}

// ---------------------------------------------------------------------------
// Kernel 2: flash attention, causal. 32-row q-tiles, 64-key k-tiles.
// Pairing (i, 127-i) -> exactly 65 k-tile units per CTA, 256 CTAs (2/SM).
// 256 threads = 16x16. Thread micro-tile: 2 rows (ty*2+i).
//   QK^T: strided columns tx+16*j  (conflict-free Ks float4, shfl softmax)
//   PV/O: contiguous columns tx*4+j (conflict-free Vs float4, float4 stores)
// All hot-loop smem traffic is LDS.128, bank-conflict-free.
// ---------------------------------------------------------------------------
#define KS_STRIDE 68
#define PS_STRIDE 72
#define QS_OFF 0
#define KS_OFF 2048                         // Qs: 32*64
#define VS_OFF (2048 + 64*KS_STRIDE)        // Ks: 64*68 = 4352
#define PS_OFF (2048 + 64*KS_STRIDE + 4096) // Vs: 64*64
#define SMEM_FLOATS (2048 + 64*KS_STRIDE + 4096 + 32*PS_STRIDE)  // 12800 = 51200 B

__device__ __forceinline__ void process_qtile(
    int b, int qt, float* Qs, float* Ks, float* Vs, float* Ps,
    float* __restrict__ out, int tid, int ty, int tx)
{
    // load Q tile (pre-scaled): 32x64 floats = 512 float4, 2/thread
    const float* __restrict__ qg = g_kqv[1] + ((size_t)b * NT + (size_t)qt * 32) * NH;
#pragma unroll
    for (int u = 0; u < 2; u++) {
        int f = tid + u * 256;
        int r = f >> 4, c4 = f & 15;
        *(float4*)&Qs[r * 64 + c4 * 4] = *(const float4*)&qg[r * NH + c4 * 4];
    }

    float m[2], l[2], o[2][4];
#pragma unroll
    for (int i = 0; i < 2; i++) {
        m[i] = -1e30f; l[i] = 0.f;
#pragma unroll
        for (int j = 0; j < 4; j++) o[i][j] = 0.f;
    }

    const int nkt = (qt >> 1) + 1;
    const int maskoff = (qt & 1) * 32;

    for (int kt = 0; kt < nkt; kt++) {
        const float* __restrict__ kg = g_kqv[0] + ((size_t)b * NT + (size_t)kt * 64) * NH;
        const float* __restrict__ vg = g_kqv[2] + ((size_t)b * NT + (size_t)kt * 64) * NH;
#pragma unroll
        for (int u = 0; u < 4; u++) {
            int f = tid + u * 256;
            int r = f >> 4, c4 = f & 15;
            float4 kv4 = *(const float4*)&kg[r * NH + c4 * 4];
            *(float4*)&Ks[r * KS_STRIDE + c4 * 4] = kv4;
            *(float4*)&Vs[r * 64 + c4 * 4] = *(const float4*)&vg[r * NH + c4 * 4];
        }
        __syncthreads();

        // S = Q K^T   (2 rows x 4 strided cols per thread)
        float s[2][4];
#pragma unroll
        for (int i = 0; i < 2; i++)
#pragma unroll
            for (int j = 0; j < 4; j++) s[i][j] = 0.f;

#pragma unroll
        for (int kk = 0; kk < 64; kk += 4) {
            float qv[2][4], kv[4][4];
#pragma unroll
            for (int i = 0; i < 2; i++) {
                float4 t4 = *(float4*)&Qs[(ty * 2 + i) * 64 + kk];
                qv[i][0] = t4.x; qv[i][1] = t4.y; qv[i][2] = t4.z; qv[i][3] = t4.w;
            }
#pragma unroll
            for (int j = 0; j < 4; j++) {
                float4 t4 = *(float4*)&Ks[(tx + 16 * j) * KS_STRIDE + kk];
                kv[j][0] = t4.x; kv[j][1] = t4.y; kv[j][2] = t4.z; kv[j][3] = t4.w;
            }
#pragma unroll
            for (int i = 0; i < 2; i++)
#pragma unroll
                for (int j = 0; j < 4; j++)
#pragma unroll
                    for (int t = 0; t < 4; t++)
                        s[i][j] = fmaf(qv[i][t], kv[j][t], s[i][j]);
        }

        if (kt == nkt - 1) {   // diagonal tile: mask key col > maskoff + row
#pragma unroll
            for (int i = 0; i < 2; i++)
#pragma unroll
                for (int j = 0; j < 4; j++)
                    if ((tx + 16 * j) > (maskoff + ty * 2 + i)) s[i][j] = -1e30f;
        }

        // online softmax (16-lane shfl groups share a row)
#pragma unroll
        for (int i = 0; i < 2; i++) {
            float rm = fmaxf(fmaxf(s[i][0], s[i][1]), fmaxf(s[i][2], s[i][3]));
            rm = fmaxf(rm, __shfl_xor_sync(0xffffffffu, rm, 8));
            rm = fmaxf(rm, __shfl_xor_sync(0xffffffffu, rm, 4));
            rm = fmaxf(rm, __shfl_xor_sync(0xffffffffu, rm, 2));
            rm = fmaxf(rm, __shfl_xor_sync(0xffffffffu, rm, 1));
            float mn   = fmaxf(m[i], rm);
            float corr = __expf(m[i] - mn);
            float p0 = __expf(s[i][0] - mn);
            float p1 = __expf(s[i][1] - mn);
            float p2 = __expf(s[i][2] - mn);
            float p3 = __expf(s[i][3] - mn);
            float rs = (p0 + p1) + (p2 + p3);
            rs += __shfl_xor_sync(0xffffffffu, rs, 8);
            rs += __shfl_xor_sync(0xffffffffu, rs, 4);
            rs += __shfl_xor_sync(0xffffffffu, rs, 2);
            rs += __shfl_xor_sync(0xffffffffu, rs, 1);
            l[i] = l[i] * corr + rs;
            m[i] = mn;
            o[i][0] *= corr; o[i][1] *= corr; o[i][2] *= corr; o[i][3] *= corr;
            int rb = (ty * 2 + i) * PS_STRIDE;
            Ps[rb + tx     ] = p0;
            Ps[rb + tx + 16] = p1;
            Ps[rb + tx + 32] = p2;
            Ps[rb + tx + 48] = p3;
        }
        __syncthreads();

        // O += P V   (2 rows x 4 contiguous cols per thread)
#pragma unroll
        for (int ss = 0; ss < 64; ss += 4) {
            float pv[2][4], vv[4][4];
#pragma unroll
            for (int i = 0; i < 2; i++) {
                float4 t4 = *(float4*)&Ps[(ty * 2 + i) * PS_STRIDE + ss];
                pv[i][0] = t4.x; pv[i][1] = t4.y; pv[i][2] = t4.z; pv[i][3] = t4.w;
            }
#pragma unroll
            for (int t = 0; t < 4; t++) {
                float4 t4 = *(float4*)&Vs[(ss + t) * 64 + tx * 4];
                vv[t][0] = t4.x; vv[t][1] = t4.y; vv[t][2] = t4.z; vv[t][3] = t4.w;
            }
#pragma unroll
            for (int i = 0; i < 2; i++)
#pragma unroll
                for (int j = 0; j < 4; j++)
#pragma unroll
                    for (int t = 0; t < 4; t++)
                        o[i][j] = fmaf(pv[i][t], vv[t][j], o[i][j]);
        }
        __syncthreads();
    }

    // epilogue: normalize, float4 store (contiguous cols tx*4)
#pragma unroll
    for (int i = 0; i < 2; i++) {
        float inv = 1.0f / l[i];
        size_t rb = ((size_t)b * NT + (size_t)qt * 32 + ty * 2 + i) * NH;
        float4 o4 = make_float4(o[i][0] * inv, o[i][1] * inv,
                                o[i][2] * inv, o[i][3] * inv);
        *(float4*)&out[rb + tx * 4] = o4;
    }
}

__global__ __launch_bounds__(256, 2) void attn_kernel(float* __restrict__ out)
{
    extern __shared__ float sm[];
    float* Qs = sm + QS_OFF;
    float* Ks = sm + KS_OFF;
    float* Vs = sm + VS_OFF;
    float* Ps = sm + PS_OFF;

    const int tid = threadIdx.x;
    const int ty  = tid >> 4;
    const int tx  = tid & 15;
    const int pp  = blockIdx.x;   // 0..63
    const int b   = blockIdx.y;   // 0..3

    // balanced pairing over 128 q-tiles: (pp) and (127-pp) -> 65 units/CTA
    process_qtile(b, 127 - pp, Qs, Ks, Vs, Ps, out, tid, ty, tx);
    process_qtile(b, pp,       Qs, Ks, Vs, Ps, out, tid, ty, tx);
}

// ---------------------------------------------------------------------------
extern "C" void kernel_launch(void* const* d_in, const int* in_sizes, int n_in,
                              void* d_out, int out_size)
{
    const float* x  = (const float*)d_in[0];
    const float* Wk = (const float*)d_in[1];
    const float* Wq = (const float*)d_in[2];
    const float* Wv = (const float*)d_in[3];
    float* out = (float*)d_out;

    cudaFuncSetAttribute(attn_kernel,
                         cudaFuncAttributeMaxDynamicSharedMemorySize,
                         SMEM_FLOATS * sizeof(float));

    proj_kernel<<<dim3(256, 3), 256>>>(x, Wk, Wq, Wv);
    attn_kernel<<<dim3(64, NB), 256, SMEM_FLOATS * sizeof(float)>>>(out);
}

// round 6
// speedup vs baseline: 1.1810x; 1.1810x over previous
#include <cuda_runtime.h>
#include <math.h>

#define NB 4
#define NT 4096
#define NC 512
#define NH 64
#define NM (NB*NT)            // 16384 rows
#define NSPLIT 4

// scratch: k,q,v projections + split-KV partials
__device__ float g_kqv[3][(size_t)NM * NH];
__device__ float g_po[NSPLIT][(size_t)NM * NH];   // unnormalized partial O
__device__ float g_pm[NSPLIT][NM];                // running max
__device__ float g_pl[NSPLIT][NM];                // running sum

// ---------------------------------------------------------------------------
// Kernel 1: fused QKV projection (unchanged — near SIMT floor).
// ---------------------------------------------------------------------------
__global__ __launch_bounds__(256) void proj_kernel(
    const float* __restrict__ x,
    const float* __restrict__ Wk,
    const float* __restrict__ Wq,
    const float* __restrict__ Wv)
{
    __shared__ float As[64 * 32];
    __shared__ float Bs[32 * 64];

    const int tid = threadIdx.x;
    const int ty  = tid >> 4;
    const int tx  = tid & 15;
    const int m0  = blockIdx.x * 64;
    const int w   = blockIdx.y;
    const float* __restrict__ W = (w == 0) ? Wk : (w == 1) ? Wq : Wv;

    float acc[4][4];
#pragma unroll
    for (int i = 0; i < 4; i++)
#pragma unroll
        for (int j = 0; j < 4; j++) acc[i][j] = 0.f;

    for (int k0 = 0; k0 < NC; k0 += 32) {
#pragma unroll
        for (int u = 0; u < 2; u++) {
            int f = tid + u * 256;
            int r = f >> 3, c = f & 7;
            *(float4*)&As[r * 32 + c * 4] =
                *(const float4*)&x[(size_t)(m0 + r) * NC + k0 + c * 4];
        }
#pragma unroll
        for (int u = 0; u < 2; u++) {
            int f = tid + u * 256;
            int r = f >> 4, c = f & 15;
            *(float4*)&Bs[r * 64 + c * 4] =
                *(const float4*)&W[(size_t)(k0 + r) * NH + c * 4];
        }
        __syncthreads();

#pragma unroll
        for (int kk = 0; kk < 32; kk += 4) {
            float av[4][4], bv[4][4];
#pragma unroll
            for (int i = 0; i < 4; i++) {
                float4 t4 = *(float4*)&As[(ty * 4 + i) * 32 + kk];
                av[i][0] = t4.x; av[i][1] = t4.y; av[i][2] = t4.z; av[i][3] = t4.w;
            }
#pragma unroll
            for (int t = 0; t < 4; t++) {
                float4 t4 = *(float4*)&Bs[(kk + t) * 64 + tx * 4];
                bv[t][0] = t4.x; bv[t][1] = t4.y; bv[t][2] = t4.z; bv[t][3] = t4.w;
            }
#pragma unroll
            for (int i = 0; i < 4; i++)
#pragma unroll
                for (int j = 0; j < 4; j++)
#pragma unroll
                    for (int t = 0; t < 4; t++)
                        acc[i][j] = fmaf(av[i][t], bv[t][j], acc[i][j]);
        }
        __syncthreads();
    }

    const float scale = (w == 1) ? 0.044194173824159216f : 1.0f;
    float* __restrict__ outb = g_kqv[w];
#pragma unroll
    for (int i = 0; i < 4; i++) {
        float4 o4 = make_float4(acc[i][0] * scale, acc[i][1] * scale,
                                acc[i][2] * scale, acc[i][3] * scale);
        *(float4*)&outb[(size_t)(m0 + ty * 4 + i) * NH + tx * 4] = o4;
    }
}

// ---------------------------------------------------------------------------
// Kernel 2: flash attention, causal, split-KV x4.
// R3 hot loop verbatim (4x4 micro-tile, crossbar-balanced). Each CTA handles
// one (b, qt64, split) with k-tiles [sp*(qt+1)/4, (sp+1)*(qt+1)/4) and writes
// unnormalized partials. 1024 CTAs, 3 CTAs/SM co-resident.
// ---------------------------------------------------------------------------
#define QS_OFF 0
#define KS_OFF 4096            // Ks: [c][k] stride 65  -> 4160 floats
#define VS_OFF (4096 + 4160)   // Vs: [s][h] stride 64  -> 4096 floats
#define PS_OFF (4096 + 4160 + 4096)
#define SMEM_FLOATS (4096 + 4160 + 4096 + 4096)   // 16448 floats = 65792 B

__global__ __launch_bounds__(256, 3) void attn_kernel()
{
    extern __shared__ float sm[];
    float* Qs = sm + QS_OFF;
    float* Ks = sm + KS_OFF;
    float* Vs = sm + VS_OFF;
    float* Ps = sm + PS_OFF;

    const int tid = threadIdx.x;
    const int ty  = tid >> 4;
    const int tx  = tid & 15;
    const int qt  = blockIdx.x;   // 0..63
    const int b   = blockIdx.y;   // 0..3
    const int sp  = blockIdx.z;   // 0..3

    const int lo = sp * (qt + 1) / NSPLIT;
    const int hi = (sp + 1) * (qt + 1) / NSPLIT;

    // load Q tile (pre-scaled): 64x64 floats = 1024 float4, 4/thread
    const float* __restrict__ qg = g_kqv[1] + ((size_t)b * NT + (size_t)qt * 64) * NH;
#pragma unroll
    for (int u = 0; u < 4; u++) {
        int f = tid + u * 256;
        int r = f >> 4, c4 = f & 15;
        *(float4*)&Qs[r * 64 + c4 * 4] = *(const float4*)&qg[r * NH + c4 * 4];
    }

    float m[4], l[4], o[4][4];
#pragma unroll
    for (int i = 0; i < 4; i++) {
        m[i] = -1e30f; l[i] = 0.f;
#pragma unroll
        for (int j = 0; j < 4; j++) o[i][j] = 0.f;
    }

    for (int kt = lo; kt < hi; kt++) {
        const float* __restrict__ kg = g_kqv[0] + ((size_t)b * NT + (size_t)kt * 64) * NH;
        const float* __restrict__ vg = g_kqv[2] + ((size_t)b * NT + (size_t)kt * 64) * NH;
#pragma unroll
        for (int u = 0; u < 4; u++) {
            int f = tid + u * 256;
            int r = f >> 4, c4 = f & 15;
            float4 kv4 = *(const float4*)&kg[r * NH + c4 * 4];
            Ks[r * 65 + c4 * 4 + 0] = kv4.x;
            Ks[r * 65 + c4 * 4 + 1] = kv4.y;
            Ks[r * 65 + c4 * 4 + 2] = kv4.z;
            Ks[r * 65 + c4 * 4 + 3] = kv4.w;
            *(float4*)&Vs[r * 64 + c4 * 4] = *(const float4*)&vg[r * NH + c4 * 4];
        }
        __syncthreads();

        // S = Q K^T  (q already scaled)
        float s[4][4];
#pragma unroll
        for (int i = 0; i < 4; i++)
#pragma unroll
            for (int j = 0; j < 4; j++) s[i][j] = 0.f;

#pragma unroll
        for (int kk = 0; kk < 64; kk += 4) {
            float qv[4][4], kv[4][4];
#pragma unroll
            for (int i = 0; i < 4; i++) {
                float4 t4 = *(float4*)&Qs[(ty * 4 + i) * 64 + kk];
                qv[i][0] = t4.x; qv[i][1] = t4.y; qv[i][2] = t4.z; qv[i][3] = t4.w;
            }
#pragma unroll
            for (int j = 0; j < 4; j++)
#pragma unroll
                for (int t = 0; t < 4; t++)
                    kv[j][t] = Ks[(tx + 16 * j) * 65 + kk + t];
#pragma unroll
            for (int i = 0; i < 4; i++)
#pragma unroll
                for (int j = 0; j < 4; j++)
#pragma unroll
                    for (int t = 0; t < 4; t++)
                        s[i][j] = fmaf(qv[i][t], kv[j][t], s[i][j]);
        }

        if (kt == qt) {   // causal mask inside diagonal tile
#pragma unroll
            for (int i = 0; i < 4; i++)
#pragma unroll
                for (int j = 0; j < 4; j++)
                    if ((tx + 16 * j) > (ty * 4 + i)) s[i][j] = -1e30f;
        }

        // online softmax update; lanes with same ty form 16-lane shfl groups
#pragma unroll
        for (int i = 0; i < 4; i++) {
            float rm = fmaxf(fmaxf(s[i][0], s[i][1]), fmaxf(s[i][2], s[i][3]));
            rm = fmaxf(rm, __shfl_xor_sync(0xffffffffu, rm, 8));
            rm = fmaxf(rm, __shfl_xor_sync(0xffffffffu, rm, 4));
            rm = fmaxf(rm, __shfl_xor_sync(0xffffffffu, rm, 2));
            rm = fmaxf(rm, __shfl_xor_sync(0xffffffffu, rm, 1));
            float mn   = fmaxf(m[i], rm);
            float corr = __expf(m[i] - mn);
            float p0 = __expf(s[i][0] - mn);
            float p1 = __expf(s[i][1] - mn);
            float p2 = __expf(s[i][2] - mn);
            float p3 = __expf(s[i][3] - mn);
            float rs = (p0 + p1) + (p2 + p3);
            rs += __shfl_xor_sync(0xffffffffu, rs, 8);
            rs += __shfl_xor_sync(0xffffffffu, rs, 4);
            rs += __shfl_xor_sync(0xffffffffu, rs, 2);
            rs += __shfl_xor_sync(0xffffffffu, rs, 1);
            l[i] = l[i] * corr + rs;
            m[i] = mn;
            o[i][0] *= corr; o[i][1] *= corr; o[i][2] *= corr; o[i][3] *= corr;
            int rb = (ty * 4 + i) * 64;
            Ps[rb + tx     ] = p0;
            Ps[rb + tx + 16] = p1;
            Ps[rb + tx + 32] = p2;
            Ps[rb + tx + 48] = p3;
        }
        __syncthreads();

        // O += P V
#pragma unroll
        for (int ss = 0; ss < 64; ss += 4) {
            float pv[4][4], vv[4][4];
#pragma unroll
            for (int i = 0; i < 4; i++) {
                float4 t4 = *(float4*)&Ps[(ty * 4 + i) * 64 + ss];
                pv[i][0] = t4.x; pv[i][1] = t4.y; pv[i][2] = t4.z; pv[i][3] = t4.w;
            }
#pragma unroll
            for (int t = 0; t < 4; t++)
#pragma unroll
                for (int j = 0; j < 4; j++)
                    vv[t][j] = Vs[(ss + t) * 64 + tx + 16 * j];
#pragma unroll
            for (int i = 0; i < 4; i++)
#pragma unroll
                for (int j = 0; j < 4; j++)
#pragma unroll
                    for (int t = 0; t < 4; t++)
                        o[i][j] = fmaf(pv[i][t], vv[t][j], o[i][j]);
        }
        __syncthreads();
    }

    // epilogue: write UNNORMALIZED partials (o, m, l)
#pragma unroll
    for (int i = 0; i < 4; i++) {
        size_t row = (size_t)b * NT + (size_t)qt * 64 + ty * 4 + i;
#pragma unroll
        for (int j = 0; j < 4; j++)
            g_po[sp][row * NH + tx + 16 * j] = o[i][j];
        if (tx == 0) {
            g_pm[sp][row] = m[i];
            g_pl[sp][row] = l[i];
        }
    }
}

// ---------------------------------------------------------------------------
// Kernel 3: combine the 4 split partials.  out = sum_s w_s * o_s / L,
// w_s = exp(m_s - M), L = sum_s l_s * w_s.   One float4 per thread.
// ---------------------------------------------------------------------------
__global__ __launch_bounds__(256) void combine_kernel(float* __restrict__ out)
{
    int idx = blockIdx.x * 256 + threadIdx.x;     // 0 .. NM*16-1
    int row = idx >> 4;
    int c4  = (idx & 15) * 4;

    float ms[NSPLIT];
    float M = -1e30f;
#pragma unroll
    for (int s = 0; s < NSPLIT; s++) {
        ms[s] = g_pm[s][row];
        M = fmaxf(M, ms[s]);
    }
    float L = 0.f, w[NSPLIT];
#pragma unroll
    for (int s = 0; s < NSPLIT; s++) {
        w[s] = __expf(ms[s] - M);
        L = fmaf(g_pl[s][row], w[s], L);
    }
    float4 acc = make_float4(0.f, 0.f, 0.f, 0.f);
#pragma unroll
    for (int s = 0; s < NSPLIT; s++) {
        float4 o4 = *(const float4*)&g_po[s][(size_t)row * NH + c4];
        acc.x = fmaf(w[s], o4.x, acc.x);
        acc.y = fmaf(w[s], o4.y, acc.y);
        acc.z = fmaf(w[s], o4.z, acc.z);
        acc.w = fmaf(w[s], o4.w, acc.w);
    }
    float inv = 1.0f / L;
    acc.x *= inv; acc.y *= inv; acc.z *= inv; acc.w *= inv;
    *(float4*)&out[(size_t)row * NH + c4] = acc;
}

// ---------------------------------------------------------------------------
extern "C" void kernel_launch(void* const* d_in, const int* in_sizes, int n_in,
                              void* d_out, int out_size)
{
    const float* x  = (const float*)d_in[0];
    const float* Wk = (const float*)d_in[1];
    const float* Wq = (const float*)d_in[2];
    const float* Wv = (const float*)d_in[3];
    float* out = (float*)d_out;

    cudaFuncSetAttribute(attn_kernel,
                         cudaFuncAttributeMaxDynamicSharedMemorySize,
                         SMEM_FLOATS * sizeof(float));

    proj_kernel<<<dim3(256, 3), 256>>>(x, Wk, Wq, Wv);
    attn_kernel<<<dim3(64, NB, NSPLIT), 256, SMEM_FLOATS * sizeof(float)>>>();
    combine_kernel<<<(NM * 16) / 256, 256>>>(out);
}

// round 8
// speedup vs baseline: 1.7889x; 1.5148x over previous
#include <cuda_runtime.h>
#include <cuda_bf16.h>
#include <math.h>
#include <stdint.h>

#define NB 4
#define NT 4096
#define NC 512
#define NH 64
#define NM (NB*NT)            // 16384 rows

// fp32 projections + bf16 hi/lo operand arrays
__device__ float g_kqv[3][(size_t)NM * NH];
__device__ __nv_bfloat16 g_qh[(size_t)NM * NH], g_ql[(size_t)NM * NH];
__device__ __nv_bfloat16 g_kh[(size_t)NM * NH], g_kl[(size_t)NM * NH];
__device__ __nv_bfloat16 g_vth[(size_t)NM * NH], g_vtl[(size_t)NM * NH]; // [b][h][s]

// ============================ helpers ======================================
__device__ __forceinline__ uint32_t smem_u32(const void* p) {
    uint32_t a;
    asm("{ .reg .u64 t; cvta.to.shared.u64 t, %1; cvt.u32.u64 %0, t; }"
        : "=r"(a) : "l"(p));
    return a;
}

__device__ __forceinline__ void ldsm4(uint32_t& r0, uint32_t& r1,
                                      uint32_t& r2, uint32_t& r3, uint32_t a) {
    asm volatile("ldmatrix.sync.aligned.m8n8.x4.shared.b16 {%0,%1,%2,%3}, [%4];"
        : "=r"(r0), "=r"(r1), "=r"(r2), "=r"(r3) : "r"(a));
}

__device__ __forceinline__ void mma16816(float& c0, float& c1, float& c2, float& c3,
                                         uint32_t a0, uint32_t a1, uint32_t a2, uint32_t a3,
                                         uint32_t b0, uint32_t b1) {
    asm volatile("mma.sync.aligned.m16n8k16.row.col.f32.bf16.bf16.f32 "
        "{%0,%1,%2,%3}, {%4,%5,%6,%7}, {%8,%9}, {%0,%1,%2,%3};"
        : "+f"(c0), "+f"(c1), "+f"(c2), "+f"(c3)
        : "r"(a0), "r"(a1), "r"(a2), "r"(a3), "r"(b0), "r"(b1));
}

__device__ __forceinline__ uint32_t pack_bf2(float a, float b, float& ra, float& rb) {
    __nv_bfloat16 ha = __float2bfloat16_rn(a);
    __nv_bfloat16 hb = __float2bfloat16_rn(b);
    ra = a - __bfloat162float(ha);
    rb = b - __bfloat162float(hb);
    return ((uint32_t)__bfloat16_as_ushort(hb) << 16) | (uint32_t)__bfloat16_as_ushort(ha);
}

// ---------------------------------------------------------------------------
// Kernel 1: fused QKV projection (SIMT, unchanged).
// ---------------------------------------------------------------------------
__global__ __launch_bounds__(256) void proj_kernel(
    const float* __restrict__ x,
    const float* __restrict__ Wk,
    const float* __restrict__ Wq,
    const float* __restrict__ Wv)
{
    __shared__ float As[64 * 32];
    __shared__ float Bs[32 * 64];

    const int tid = threadIdx.x;
    const int ty  = tid >> 4;
    const int tx  = tid & 15;
    const int m0  = blockIdx.x * 64;
    const int w   = blockIdx.y;
    const float* __restrict__ W = (w == 0) ? Wk : (w == 1) ? Wq : Wv;

    float acc[4][4];
#pragma unroll
    for (int i = 0; i < 4; i++)
#pragma unroll
        for (int j = 0; j < 4; j++) acc[i][j] = 0.f;

    for (int k0 = 0; k0 < NC; k0 += 32) {
#pragma unroll
        for (int u = 0; u < 2; u++) {
            int f = tid + u * 256;
            int r = f >> 3, c = f & 7;
            *(float4*)&As[r * 32 + c * 4] =
                *(const float4*)&x[(size_t)(m0 + r) * NC + k0 + c * 4];
        }
#pragma unroll
        for (int u = 0; u < 2; u++) {
            int f = tid + u * 256;
            int r = f >> 4, c = f & 15;
            *(float4*)&Bs[r * 64 + c * 4] =
                *(const float4*)&W[(size_t)(k0 + r) * NH + c * 4];
        }
        __syncthreads();

#pragma unroll
        for (int kk = 0; kk < 32; kk += 4) {
            float av[4][4], bv[4][4];
#pragma unroll
            for (int i = 0; i < 4; i++) {
                float4 t4 = *(float4*)&As[(ty * 4 + i) * 32 + kk];
                av[i][0] = t4.x; av[i][1] = t4.y; av[i][2] = t4.z; av[i][3] = t4.w;
            }
#pragma unroll
            for (int t = 0; t < 4; t++) {
                float4 t4 = *(float4*)&Bs[(kk + t) * 64 + tx * 4];
                bv[t][0] = t4.x; bv[t][1] = t4.y; bv[t][2] = t4.z; bv[t][3] = t4.w;
            }
#pragma unroll
            for (int i = 0; i < 4; i++)
#pragma unroll
                for (int j = 0; j < 4; j++)
#pragma unroll
                    for (int t = 0; t < 4; t++)
                        acc[i][j] = fmaf(av[i][t], bv[t][j], acc[i][j]);
        }
        __syncthreads();
    }

    const float scale = (w == 1) ? 0.044194173824159216f : 1.0f;
    float* __restrict__ outb = g_kqv[w];
#pragma unroll
    for (int i = 0; i < 4; i++) {
        float4 o4 = make_float4(acc[i][0] * scale, acc[i][1] * scale,
                                acc[i][2] * scale, acc[i][3] * scale);
        *(float4*)&outb[(size_t)(m0 + ty * 4 + i) * NH + tx * 4] = o4;
    }
}

// ---------------------------------------------------------------------------
// Kernel 2a: q, k fp32 -> bf16 hi/lo
// ---------------------------------------------------------------------------
__global__ __launch_bounds__(256) void conv_qk_kernel()
{
    size_t i = (size_t)blockIdx.x * 256 + threadIdx.x;
    size_t base = i * 4;

    float4 q4 = *(const float4*)&g_kqv[1][base];
    float4 k4 = *(const float4*)&g_kqv[0][base];
    float r0, r1, r2, r3;

    uint2 qh, ql;
    qh.x = pack_bf2(q4.x, q4.y, r0, r1);
    qh.y = pack_bf2(q4.z, q4.w, r2, r3);
    ql.x = pack_bf2(r0, r1, r0, r1);
    ql.y = pack_bf2(r2, r3, r2, r3);
    *(uint2*)&g_qh[base] = qh;
    *(uint2*)&g_ql[base] = ql;

    uint2 kh, kl;
    kh.x = pack_bf2(k4.x, k4.y, r0, r1);
    kh.y = pack_bf2(k4.z, k4.w, r2, r3);
    kl.x = pack_bf2(r0, r1, r0, r1);
    kl.y = pack_bf2(r2, r3, r2, r3);
    *(uint2*)&g_kh[base] = kh;
    *(uint2*)&g_kl[base] = kl;
}

// ---------------------------------------------------------------------------
// Kernel 2b: v fp32 [b][s][h] -> vt hi/lo bf16 [b][h][s]
// ---------------------------------------------------------------------------
__global__ __launch_bounds__(256) void conv_vt_kernel()
{
    __shared__ float t[64][65];
    const int b  = blockIdx.y;
    const int st = blockIdx.x;
    const int tid = threadIdx.x;

    const float* vp = g_kqv[2] + ((size_t)b * NT + (size_t)st * 64) * NH;
#pragma unroll
    for (int u = 0; u < 4; u++) {
        int f = tid + u * 256;
        int r = f >> 4, c4 = f & 15;
        float4 v4 = *(const float4*)&vp[(size_t)r * NH + c4 * 4];
        t[r][c4 * 4 + 0] = v4.x; t[r][c4 * 4 + 1] = v4.y;
        t[r][c4 * 4 + 2] = v4.z; t[r][c4 * 4 + 3] = v4.w;
    }
    __syncthreads();

#pragma unroll
    for (int u = 0; u < 4; u++) {
        int f = tid + u * 256;
        int h = f >> 4, c4 = f & 15;
        float s0 = t[c4 * 4 + 0][h], s1 = t[c4 * 4 + 1][h];
        float s2 = t[c4 * 4 + 2][h], s3 = t[c4 * 4 + 3][h];
        float r0, r1, r2, r3;
        uint2 hi, lo;
        hi.x = pack_bf2(s0, s1, r0, r1);
        hi.y = pack_bf2(s2, s3, r2, r3);
        lo.x = pack_bf2(r0, r1, r0, r1);
        lo.y = pack_bf2(r2, r3, r2, r3);
        size_t e = ((size_t)b * NH + h) * NT + (size_t)st * 64 + c4 * 4;
        *(uint2*)&g_vth[e] = hi;
        *(uint2*)&g_vtl[e] = lo;
    }
}

// ---------------------------------------------------------------------------
// Kernel 3: FA2-style attention on mma.sync (bf16 hi/lo, fp32 accum).
// CTA = 128 thr / 4 warps; q-tile 64 rows (16/warp); k-tiles of 64 keys.
// No-max softmax (scores bounded ~|2|), in-kernel normalization.
// smem rows stride 72 bf16 (144B) -> conflict-free ldmatrix.
// ---------------------------------------------------------------------------
#define KSTR 72

__global__ __launch_bounds__(128, 3) void attn_kernel(float* __restrict__ out)
{
    __shared__ __nv_bfloat16 sKh[64 * KSTR];
    __shared__ __nv_bfloat16 sKl[64 * KSTR];
    __shared__ __nv_bfloat16 sVh[64 * KSTR];
    __shared__ __nv_bfloat16 sVl[64 * KSTR];

    const int tid  = threadIdx.x;
    const int w    = tid >> 5;
    const int lane = tid & 31;
    const int g    = lane >> 2;          // row-in-group
    const int l4   = lane & 3;           // col pair
    const int qt   = 63 - blockIdx.x;    // LPT: biggest first
    const int b    = blockIdx.y;
    const int nu   = qt + 1;             // 64-key tiles

    const uint32_t kh_b = smem_u32(sKh);
    const uint32_t kl_b = smem_u32(sKl);
    const uint32_t vh_b = smem_u32(sVh);
    const uint32_t vl_b = smem_u32(sVl);

    // ldmatrix lane->addr offsets (in elements)
    const int rowA = lane & 15;                          // A frag: rows 0..15
    const int kofA = (lane & 16) >> 1;                   // +8 dims for mats 2,3
    const int laneA = rowA * KSTR + kofA;
    const int rowB = (lane & 7) | ((lane & 16) >> 1);    // B frag: +8 rows for mats 2,3
    const int kofB = (lane & 8);                         // +8 dims for mats 1,3
    const int laneB = rowB * KSTR + kofB;

    // ---- stage Q hi then lo through sKh, capture register fragments ----
    uint32_t qh[4][4], ql[4][4];
    {
        const char* qhp = (const char*)(g_qh + ((size_t)b * NT + (size_t)qt * 64) * NH);
        const char* qlp = (const char*)(g_ql + ((size_t)b * NT + (size_t)qt * 64) * NH);
#pragma unroll
        for (int u = 0; u < 4; u++) {
            int f = tid + u * 128;
            int r = f >> 3, c = f & 7;
            *(uint4*)((char*)sKh + (r * KSTR) * 2 + c * 16) =
                *(const uint4*)(qhp + r * 128 + c * 16);
        }
        __syncthreads();
#pragma unroll
        for (int kc = 0; kc < 4; kc++)
            ldsm4(qh[kc][0], qh[kc][1], qh[kc][2], qh[kc][3],
                  kh_b + (uint32_t)(w * 16 * KSTR + kc * 16 + laneA) * 2);
        __syncthreads();
#pragma unroll
        for (int u = 0; u < 4; u++) {
            int f = tid + u * 128;
            int r = f >> 3, c = f & 7;
            *(uint4*)((char*)sKh + (r * KSTR) * 2 + c * 16) =
                *(const uint4*)(qlp + r * 128 + c * 16);
        }
        __syncthreads();
#pragma unroll
        for (int kc = 0; kc < 4; kc++)
            ldsm4(ql[kc][0], ql[kc][1], ql[kc][2], ql[kc][3],
                  kh_b + (uint32_t)(w * 16 * KSTR + kc * 16 + laneA) * 2);
    }

    float o[8][4];
#pragma unroll
    for (int j = 0; j < 8; j++)
#pragma unroll
        for (int c = 0; c < 4; c++) o[j][c] = 0.f;
    float lth0 = 0.f, lth1 = 0.f;

    const int r0g = qt * 64 + w * 16 + g;    // global q row (this thread, low)
    const int r1g = r0g + 8;

    for (int kt = 0; kt < nu; kt++) {
        __syncthreads();   // protect prior-iter ldmatrix reads (and Q staging)
        // fill K hi/lo and V^T hi/lo tiles (each 64 rows x 128B)
        {
            const char* khp = (const char*)(g_kh + ((size_t)b * NT + (size_t)kt * 64) * NH);
            const char* klp = (const char*)(g_kl + ((size_t)b * NT + (size_t)kt * 64) * NH);
            const char* vhp = (const char*)(g_vth + (size_t)b * NH * NT + (size_t)kt * 64);
            const char* vlp = (const char*)(g_vtl + (size_t)b * NH * NT + (size_t)kt * 64);
#pragma unroll
            for (int u = 0; u < 4; u++) {
                int f = tid + u * 128;
                int r = f >> 3, c = f & 7;
                uint32_t so = (uint32_t)(r * KSTR) * 2 + c * 16;
                *(uint4*)((char*)sKh + so) = *(const uint4*)(khp + r * 128 + c * 16);
                *(uint4*)((char*)sKl + so) = *(const uint4*)(klp + r * 128 + c * 16);
                *(uint4*)((char*)sVh + so) = *(const uint4*)(vhp + (size_t)r * (NT * 2) + c * 16);
                *(uint4*)((char*)sVl + so) = *(const uint4*)(vlp + (size_t)r * (NT * 2) + c * 16);
            }
        }
        __syncthreads();

        // ---- S = Qhi*Khi + Qlo*Khi + Qhi*Klo ----
        float s[8][4];
#pragma unroll
        for (int j = 0; j < 8; j++)
#pragma unroll
            for (int c = 0; c < 4; c++) s[j][c] = 0.f;

#pragma unroll
        for (int jp = 0; jp < 4; jp++) {     // key blocks 16jp..16jp+15
#pragma unroll
            for (int kc = 0; kc < 4; kc++) {
                uint32_t off = (uint32_t)(jp * 16 * KSTR + kc * 16 + laneB) * 2;
                uint32_t b0, b1, b2, b3;
                ldsm4(b0, b1, b2, b3, kh_b + off);
                mma16816(s[2*jp][0], s[2*jp][1], s[2*jp][2], s[2*jp][3],
                         qh[kc][0], qh[kc][1], qh[kc][2], qh[kc][3], b0, b1);
                mma16816(s[2*jp+1][0], s[2*jp+1][1], s[2*jp+1][2], s[2*jp+1][3],
                         qh[kc][0], qh[kc][1], qh[kc][2], qh[kc][3], b2, b3);
                mma16816(s[2*jp][0], s[2*jp][1], s[2*jp][2], s[2*jp][3],
                         ql[kc][0], ql[kc][1], ql[kc][2], ql[kc][3], b0, b1);
                mma16816(s[2*jp+1][0], s[2*jp+1][1], s[2*jp+1][2], s[2*jp+1][3],
                         ql[kc][0], ql[kc][1], ql[kc][2], ql[kc][3], b2, b3);
                ldsm4(b0, b1, b2, b3, kl_b + off);
                mma16816(s[2*jp][0], s[2*jp][1], s[2*jp][2], s[2*jp][3],
                         qh[kc][0], qh[kc][1], qh[kc][2], qh[kc][3], b0, b1);
                mma16816(s[2*jp+1][0], s[2*jp+1][1], s[2*jp+1][2], s[2*jp+1][3],
                         qh[kc][0], qh[kc][1], qh[kc][2], qh[kc][3], b2, b3);
            }
        }

        // ---- exp + causal mask + hi/lo split into PV A-fragments ----
        uint32_t paH[8][2], paL[8][2];
#pragma unroll
        for (int j = 0; j < 8; j++) {
            int cb = kt * 64 + 8 * j + 2 * l4;
            float p00 = (cb     <= r0g) ? __expf(s[j][0]) : 0.f;
            float p01 = (cb + 1 <= r0g) ? __expf(s[j][1]) : 0.f;
            float p10 = (cb     <= r1g) ? __expf(s[j][2]) : 0.f;
            float p11 = (cb + 1 <= r1g) ? __expf(s[j][3]) : 0.f;
            lth0 += p00 + p01;
            lth1 += p10 + p11;
            float e0, e1, e2, e3;
            paH[j][0] = pack_bf2(p00, p01, e0, e1);
            paH[j][1] = pack_bf2(p10, p11, e2, e3);
            paL[j][0] = pack_bf2(e0, e1, e0, e1);
            paL[j][1] = pack_bf2(e2, e3, e2, e3);
        }

        // ---- O += Phi*Vhi + Plo*Vhi + Phi*Vlo ----
#pragma unroll
        for (int np = 0; np < 4; np++) {     // dim blocks 16np..16np+15
#pragma unroll
            for (int kc = 0; kc < 4; kc++) {
                uint32_t off = (uint32_t)(np * 16 * KSTR + kc * 16 + laneB) * 2;
                uint32_t b0, b1, b2, b3;
                uint32_t a0 = paH[2*kc][0], a1 = paH[2*kc][1];
                uint32_t a2 = paH[2*kc+1][0], a3 = paH[2*kc+1][1];
                uint32_t c0 = paL[2*kc][0], c1 = paL[2*kc][1];
                uint32_t c2 = paL[2*kc+1][0], c3 = paL[2*kc+1][1];
                ldsm4(b0, b1, b2, b3, vh_b + off);
                mma16816(o[2*np][0], o[2*np][1], o[2*np][2], o[2*np][3],
                         a0, a1, a2, a3, b0, b1);
                mma16816(o[2*np+1][0], o[2*np+1][1], o[2*np+1][2], o[2*np+1][3],
                         a0, a1, a2, a3, b2, b3);
                mma16816(o[2*np][0], o[2*np][1], o[2*np][2], o[2*np][3],
                         c0, c1, c2, c3, b0, b1);
                mma16816(o[2*np+1][0], o[2*np+1][1], o[2*np+1][2], o[2*np+1][3],
                         c0, c1, c2, c3, b2, b3);
                ldsm4(b0, b1, b2, b3, vl_b + off);
                mma16816(o[2*np][0], o[2*np][1], o[2*np][2], o[2*np][3],
                         a0, a1, a2, a3, b0, b1);
                mma16816(o[2*np+1][0], o[2*np+1][1], o[2*np+1][2], o[2*np+1][3],
                         a0, a1, a2, a3, b2, b3);
            }
        }
    }

    // ---- row sums across the 4 lanes sharing each row; normalize; store ----
    lth0 += __shfl_xor_sync(0xffffffffu, lth0, 1);
    lth0 += __shfl_xor_sync(0xffffffffu, lth0, 2);
    lth1 += __shfl_xor_sync(0xffffffffu, lth1, 1);
    lth1 += __shfl_xor_sync(0xffffffffu, lth1, 2);
    float inv0 = 1.0f / lth0;
    float inv1 = 1.0f / lth1;

    float* op0 = out + ((size_t)b * NT + r0g) * NH;
    float* op1 = out + ((size_t)b * NT + r1g) * NH;
#pragma unroll
    for (int j = 0; j < 8; j++) {
        int col = 8 * j + 2 * l4;
        *(float2*)&op0[col] = make_float2(o[j][0] * inv0, o[j][1] * inv0);
        *(float2*)&op1[col] = make_float2(o[j][2] * inv1, o[j][3] * inv1);
    }
}

// ---------------------------------------------------------------------------
extern "C" void kernel_launch(void* const* d_in, const int* in_sizes, int n_in,
                              void* d_out, int out_size)
{
    const float* x  = (const float*)d_in[0];
    const float* Wk = (const float*)d_in[1];
    const float* Wq = (const float*)d_in[2];
    const float* Wv = (const float*)d_in[3];
    float* out = (float*)d_out;

    proj_kernel<<<dim3(256, 3), 256>>>(x, Wk, Wq, Wv);
    conv_qk_kernel<<<1024, 256>>>();
    conv_vt_kernel<<<dim3(64, NB), 256>>>();
    attn_kernel<<<dim3(64, NB), 128>>>(out);
}

// round 9
// speedup vs baseline: 2.3645x; 1.3218x over previous
#include <cuda_runtime.h>
#include <cuda_bf16.h>
#include <math.h>
#include <stdint.h>

#define NB 4
#define NT 4096
#define NC 512
#define NH 64
#define NM (NB*NT)            // 16384 rows

// fp32 projections + bf16 hi/lo operand arrays + split-KV partials
__device__ float g_kqv[3][(size_t)NM * NH];
__device__ __nv_bfloat16 g_qh[(size_t)NM * NH], g_ql[(size_t)NM * NH];
__device__ __nv_bfloat16 g_kh[(size_t)NM * NH], g_kl[(size_t)NM * NH];
__device__ __nv_bfloat16 g_vth[(size_t)NM * NH], g_vtl[(size_t)NM * NH]; // [b][h][s]
__device__ float g_po[2][(size_t)NM * NH];
__device__ float g_pl[2][NM];

// ============================ helpers ======================================
__device__ __forceinline__ uint32_t smem_u32(const void* p) {
    uint32_t a;
    asm("{ .reg .u64 t; cvta.to.shared.u64 t, %1; cvt.u32.u64 %0, t; }"
        : "=r"(a) : "l"(p));
    return a;
}

__device__ __forceinline__ void ldsm4(uint32_t& r0, uint32_t& r1,
                                      uint32_t& r2, uint32_t& r3, uint32_t a) {
    asm volatile("ldmatrix.sync.aligned.m8n8.x4.shared.b16 {%0,%1,%2,%3}, [%4];"
        : "=r"(r0), "=r"(r1), "=r"(r2), "=r"(r3) : "r"(a));
}

__device__ __forceinline__ void mma16816(float& c0, float& c1, float& c2, float& c3,
                                         uint32_t a0, uint32_t a1, uint32_t a2, uint32_t a3,
                                         uint32_t b0, uint32_t b1) {
    asm volatile("mma.sync.aligned.m16n8k16.row.col.f32.bf16.bf16.f32 "
        "{%0,%1,%2,%3}, {%4,%5,%6,%7}, {%8,%9}, {%0,%1,%2,%3};"
        : "+f"(c0), "+f"(c1), "+f"(c2), "+f"(c3)
        : "r"(a0), "r"(a1), "r"(a2), "r"(a3), "r"(b0), "r"(b1));
}

__device__ __forceinline__ uint32_t pack_bf2(float a, float b, float& ra, float& rb) {
    __nv_bfloat16 ha = __float2bfloat16_rn(a);
    __nv_bfloat16 hb = __float2bfloat16_rn(b);
    ra = a - __bfloat162float(ha);
    rb = b - __bfloat162float(hb);
    return ((uint32_t)__bfloat16_as_ushort(hb) << 16) | (uint32_t)__bfloat16_as_ushort(ha);
}

#define CP16(dst, src) \
    asm volatile("cp.async.cg.shared.global [%0], [%1], 16;" \
        :: "r"(dst), "l"(src) : "memory")
#define CP_COMMIT() asm volatile("cp.async.commit_group;" ::: "memory")
#define CP_WAIT0()  asm volatile("cp.async.wait_group 0;" ::: "memory")

// ---------------------------------------------------------------------------
// Kernel 1: fused QKV projection (SIMT, unchanged).
// ---------------------------------------------------------------------------
__global__ __launch_bounds__(256) void proj_kernel(
    const float* __restrict__ x,
    const float* __restrict__ Wk,
    const float* __restrict__ Wq,
    const float* __restrict__ Wv)
{
    __shared__ float As[64 * 32];
    __shared__ float Bs[32 * 64];

    const int tid = threadIdx.x;
    const int ty  = tid >> 4;
    const int tx  = tid & 15;
    const int m0  = blockIdx.x * 64;
    const int w   = blockIdx.y;
    const float* __restrict__ W = (w == 0) ? Wk : (w == 1) ? Wq : Wv;

    float acc[4][4];
#pragma unroll
    for (int i = 0; i < 4; i++)
#pragma unroll
        for (int j = 0; j < 4; j++) acc[i][j] = 0.f;

    for (int k0 = 0; k0 < NC; k0 += 32) {
#pragma unroll
        for (int u = 0; u < 2; u++) {
            int f = tid + u * 256;
            int r = f >> 3, c = f & 7;
            *(float4*)&As[r * 32 + c * 4] =
                *(const float4*)&x[(size_t)(m0 + r) * NC + k0 + c * 4];
        }
#pragma unroll
        for (int u = 0; u < 2; u++) {
            int f = tid + u * 256;
            int r = f >> 4, c = f & 15;
            *(float4*)&Bs[r * 64 + c * 4] =
                *(const float4*)&W[(size_t)(k0 + r) * NH + c * 4];
        }
        __syncthreads();

#pragma unroll
        for (int kk = 0; kk < 32; kk += 4) {
            float av[4][4], bv[4][4];
#pragma unroll
            for (int i = 0; i < 4; i++) {
                float4 t4 = *(float4*)&As[(ty * 4 + i) * 32 + kk];
                av[i][0] = t4.x; av[i][1] = t4.y; av[i][2] = t4.z; av[i][3] = t4.w;
            }
#pragma unroll
            for (int t = 0; t < 4; t++) {
                float4 t4 = *(float4*)&Bs[(kk + t) * 64 + tx * 4];
                bv[t][0] = t4.x; bv[t][1] = t4.y; bv[t][2] = t4.z; bv[t][3] = t4.w;
            }
#pragma unroll
            for (int i = 0; i < 4; i++)
#pragma unroll
                for (int j = 0; j < 4; j++)
#pragma unroll
                    for (int t = 0; t < 4; t++)
                        acc[i][j] = fmaf(av[i][t], bv[t][j], acc[i][j]);
        }
        __syncthreads();
    }

    const float scale = (w == 1) ? 0.044194173824159216f : 1.0f;
    float* __restrict__ outb = g_kqv[w];
#pragma unroll
    for (int i = 0; i < 4; i++) {
        float4 o4 = make_float4(acc[i][0] * scale, acc[i][1] * scale,
                                acc[i][2] * scale, acc[i][3] * scale);
        *(float4*)&outb[(size_t)(m0 + ty * 4 + i) * NH + tx * 4] = o4;
    }
}

// ---------------------------------------------------------------------------
// Kernel 2a: q, k fp32 -> bf16 hi/lo
// ---------------------------------------------------------------------------
__global__ __launch_bounds__(256) void conv_qk_kernel()
{
    size_t i = (size_t)blockIdx.x * 256 + threadIdx.x;
    size_t base = i * 4;

    float4 q4 = *(const float4*)&g_kqv[1][base];
    float4 k4 = *(const float4*)&g_kqv[0][base];
    float r0, r1, r2, r3;

    uint2 qh, ql;
    qh.x = pack_bf2(q4.x, q4.y, r0, r1);
    qh.y = pack_bf2(q4.z, q4.w, r2, r3);
    ql.x = pack_bf2(r0, r1, r0, r1);
    ql.y = pack_bf2(r2, r3, r2, r3);
    *(uint2*)&g_qh[base] = qh;
    *(uint2*)&g_ql[base] = ql;

    uint2 kh, kl;
    kh.x = pack_bf2(k4.x, k4.y, r0, r1);
    kh.y = pack_bf2(k4.z, k4.w, r2, r3);
    kl.x = pack_bf2(r0, r1, r0, r1);
    kl.y = pack_bf2(r2, r3, r2, r3);
    *(uint2*)&g_kh[base] = kh;
    *(uint2*)&g_kl[base] = kl;
}

// ---------------------------------------------------------------------------
// Kernel 2b: v fp32 [b][s][h] -> vt hi/lo bf16 [b][h][s]
// ---------------------------------------------------------------------------
__global__ __launch_bounds__(256) void conv_vt_kernel()
{
    __shared__ float t[64][65];
    const int b  = blockIdx.y;
    const int st = blockIdx.x;
    const int tid = threadIdx.x;

    const float* vp = g_kqv[2] + ((size_t)b * NT + (size_t)st * 64) * NH;
#pragma unroll
    for (int u = 0; u < 4; u++) {
        int f = tid + u * 256;
        int r = f >> 4, c4 = f & 15;
        float4 v4 = *(const float4*)&vp[(size_t)r * NH + c4 * 4];
        t[r][c4 * 4 + 0] = v4.x; t[r][c4 * 4 + 1] = v4.y;
        t[r][c4 * 4 + 2] = v4.z; t[r][c4 * 4 + 3] = v4.w;
    }
    __syncthreads();

#pragma unroll
    for (int u = 0; u < 4; u++) {
        int f = tid + u * 256;
        int h = f >> 4, c4 = f & 15;
        float s0 = t[c4 * 4 + 0][h], s1 = t[c4 * 4 + 1][h];
        float s2 = t[c4 * 4 + 2][h], s3 = t[c4 * 4 + 3][h];
        float r0, r1, r2, r3;
        uint2 hi, lo;
        hi.x = pack_bf2(s0, s1, r0, r1);
        hi.y = pack_bf2(s2, s3, r2, r3);
        lo.x = pack_bf2(r0, r1, r0, r1);
        lo.y = pack_bf2(r2, r3, r2, r3);
        size_t e = ((size_t)b * NH + h) * NT + (size_t)st * 64 + c4 * 4;
        *(uint2*)&g_vth[e] = hi;
        *(uint2*)&g_vtl[e] = lo;
    }
}

// ---------------------------------------------------------------------------
// Kernel 3: FA2-style attention on mma.sync, split-KV x2, cp.async
// double-buffered tile fills.  CTA = 128 thr / 4 warps, q-tile 64 rows.
// No-max softmax; unnormalized partials (o, l) to global; combine merges.
// ---------------------------------------------------------------------------
#define KSTR 72
#define TILE_B (64 * KSTR * 2)      // 9216 B per array
#define BUF_B  (4 * TILE_B)         // 36864 B: {Kh, Kl, Vh, Vl}
#define SMEM_B (2 * BUF_B)          // 73728 B

__device__ __forceinline__ void fill_tile(uint32_t dstb, int b, int kt, int tid)
{
    const char* khp = (const char*)(g_kh + ((size_t)b * NT + (size_t)kt * 64) * NH);
    const char* klp = (const char*)(g_kl + ((size_t)b * NT + (size_t)kt * 64) * NH);
    const char* vhp = (const char*)(g_vth + (size_t)b * NH * NT + (size_t)kt * 64);
    const char* vlp = (const char*)(g_vtl + (size_t)b * NH * NT + (size_t)kt * 64);
#pragma unroll
    for (int u = 0; u < 4; u++) {
        int f = tid + u * 128;
        int r = f >> 3, c = f & 7;
        uint32_t so = (uint32_t)(r * KSTR) * 2 + c * 16;
        size_t go = (size_t)r * 128 + c * 16;
        size_t vo = (size_t)r * (NT * 2) + c * 16;
        CP16(dstb + so,              khp + go);
        CP16(dstb + TILE_B + so,     klp + go);
        CP16(dstb + 2 * TILE_B + so, vhp + vo);
        CP16(dstb + 3 * TILE_B + so, vlp + vo);
    }
}

__global__ __launch_bounds__(128, 3) void attn_kernel()
{
    extern __shared__ char smc[];
    const uint32_t smb = smem_u32(smc);

    const int tid  = threadIdx.x;
    const int w    = tid >> 5;
    const int lane = tid & 31;
    const int g    = lane >> 2;
    const int l4   = lane & 3;
    const int qt   = 63 - (blockIdx.x >> 1);   // LPT
    const int sp   = blockIdx.x & 1;
    const int b    = blockIdx.y;
    const int lo   = sp * (qt + 1) / 2;
    const int hi   = (sp + 1) * (qt + 1) / 2;
    const int nu   = hi - lo;

    // ldmatrix lane->addr offsets (elements)
    const int rowA = lane & 15;
    const int kofA = (lane & 16) >> 1;
    const int laneA = rowA * KSTR + kofA;
    const int rowB = (lane & 7) | ((lane & 16) >> 1);
    const int kofB = (lane & 8);
    const int laneB = rowB * KSTR + kofB;

    // ---- stage Q hi then lo through buf1's Kh area; capture fragments ----
    uint32_t qh[4][4], ql[4][4];
    {
        char* qs = smc + BUF_B;
        const uint32_t qsb = smb + BUF_B;
        const char* qhp = (const char*)(g_qh + ((size_t)b * NT + (size_t)qt * 64) * NH);
        const char* qlp = (const char*)(g_ql + ((size_t)b * NT + (size_t)qt * 64) * NH);
#pragma unroll
        for (int u = 0; u < 4; u++) {
            int f = tid + u * 128;
            int r = f >> 3, c = f & 7;
            *(uint4*)(qs + (r * KSTR) * 2 + c * 16) = *(const uint4*)(qhp + r * 128 + c * 16);
        }
        __syncthreads();
#pragma unroll
        for (int kc = 0; kc < 4; kc++)
            ldsm4(qh[kc][0], qh[kc][1], qh[kc][2], qh[kc][3],
                  qsb + (uint32_t)(w * 16 * KSTR + kc * 16 + laneA) * 2);
        __syncthreads();
#pragma unroll
        for (int u = 0; u < 4; u++) {
            int f = tid + u * 128;
            int r = f >> 3, c = f & 7;
            *(uint4*)(qs + (r * KSTR) * 2 + c * 16) = *(const uint4*)(qlp + r * 128 + c * 16);
        }
        __syncthreads();
#pragma unroll
        for (int kc = 0; kc < 4; kc++)
            ldsm4(ql[kc][0], ql[kc][1], ql[kc][2], ql[kc][3],
                  qsb + (uint32_t)(w * 16 * KSTR + kc * 16 + laneA) * 2);
        __syncthreads();
    }

    float o[8][4];
#pragma unroll
    for (int j = 0; j < 8; j++)
#pragma unroll
        for (int c = 0; c < 4; c++) o[j][c] = 0.f;
    float lth0 = 0.f, lth1 = 0.f;

    const int r0g = qt * 64 + w * 16 + g;
    const int r1g = r0g + 8;

    if (nu > 0) { fill_tile(smb, b, lo, tid); CP_COMMIT(); }

    for (int u = 0; u < nu; u++) {
        const int kt = lo + u;
        const uint32_t bcur = smb + (u & 1) * BUF_B;
        const uint32_t kh_b = bcur;
        const uint32_t kl_b = bcur + TILE_B;
        const uint32_t vh_b = bcur + 2 * TILE_B;
        const uint32_t vl_b = bcur + 3 * TILE_B;

        CP_WAIT0();
        __syncthreads();                       // tile u ready; prior reads done
        if (u + 1 < nu) {
            fill_tile(smb + ((u + 1) & 1) * BUF_B, b, kt + 1, tid);
            CP_COMMIT();
        }

        // ---- S = Qhi*Khi + Qlo*Khi + Qhi*Klo ----
        float s[8][4];
#pragma unroll
        for (int j = 0; j < 8; j++)
#pragma unroll
            for (int c = 0; c < 4; c++) s[j][c] = 0.f;

#pragma unroll
        for (int jp = 0; jp < 4; jp++) {
#pragma unroll
            for (int kc = 0; kc < 4; kc++) {
                uint32_t off = (uint32_t)(jp * 16 * KSTR + kc * 16 + laneB) * 2;
                uint32_t b0, b1, b2, b3;
                ldsm4(b0, b1, b2, b3, kh_b + off);
                mma16816(s[2*jp][0], s[2*jp][1], s[2*jp][2], s[2*jp][3],
                         qh[kc][0], qh[kc][1], qh[kc][2], qh[kc][3], b0, b1);
                mma16816(s[2*jp+1][0], s[2*jp+1][1], s[2*jp+1][2], s[2*jp+1][3],
                         qh[kc][0], qh[kc][1], qh[kc][2], qh[kc][3], b2, b3);
                mma16816(s[2*jp][0], s[2*jp][1], s[2*jp][2], s[2*jp][3],
                         ql[kc][0], ql[kc][1], ql[kc][2], ql[kc][3], b0, b1);
                mma16816(s[2*jp+1][0], s[2*jp+1][1], s[2*jp+1][2], s[2*jp+1][3],
                         ql[kc][0], ql[kc][1], ql[kc][2], ql[kc][3], b2, b3);
                ldsm4(b0, b1, b2, b3, kl_b + off);
                mma16816(s[2*jp][0], s[2*jp][1], s[2*jp][2], s[2*jp][3],
                         qh[kc][0], qh[kc][1], qh[kc][2], qh[kc][3], b0, b1);
                mma16816(s[2*jp+1][0], s[2*jp+1][1], s[2*jp+1][2], s[2*jp+1][3],
                         qh[kc][0], qh[kc][1], qh[kc][2], qh[kc][3], b2, b3);
            }
        }

        // ---- exp + causal mask + hi/lo split into PV A-fragments ----
        uint32_t paH[8][2], paL[8][2];
#pragma unroll
        for (int j = 0; j < 8; j++) {
            int cb = kt * 64 + 8 * j + 2 * l4;
            float p00 = (cb     <= r0g) ? __expf(s[j][0]) : 0.f;
            float p01 = (cb + 1 <= r0g) ? __expf(s[j][1]) : 0.f;
            float p10 = (cb     <= r1g) ? __expf(s[j][2]) : 0.f;
            float p11 = (cb + 1 <= r1g) ? __expf(s[j][3]) : 0.f;
            lth0 += p00 + p01;
            lth1 += p10 + p11;
            float e0, e1, e2, e3;
            paH[j][0] = pack_bf2(p00, p01, e0, e1);
            paH[j][1] = pack_bf2(p10, p11, e2, e3);
            paL[j][0] = pack_bf2(e0, e1, e0, e1);
            paL[j][1] = pack_bf2(e2, e3, e2, e3);
        }

        // ---- O += Phi*Vhi + Plo*Vhi + Phi*Vlo ----
#pragma unroll
        for (int np = 0; np < 4; np++) {
#pragma unroll
            for (int kc = 0; kc < 4; kc++) {
                uint32_t off = (uint32_t)(np * 16 * KSTR + kc * 16 + laneB) * 2;
                uint32_t b0, b1, b2, b3;
                uint32_t a0 = paH[2*kc][0], a1 = paH[2*kc][1];
                uint32_t a2 = paH[2*kc+1][0], a3 = paH[2*kc+1][1];
                uint32_t c0 = paL[2*kc][0], c1 = paL[2*kc][1];
                uint32_t c2 = paL[2*kc+1][0], c3 = paL[2*kc+1][1];
                ldsm4(b0, b1, b2, b3, vh_b + off);
                mma16816(o[2*np][0], o[2*np][1], o[2*np][2], o[2*np][3],
                         a0, a1, a2, a3, b0, b1);
                mma16816(o[2*np+1][0], o[2*np+1][1], o[2*np+1][2], o[2*np+1][3],
                         a0, a1, a2, a3, b2, b3);
                mma16816(o[2*np][0], o[2*np][1], o[2*np][2], o[2*np][3],
                         c0, c1, c2, c3, b0, b1);
                mma16816(o[2*np+1][0], o[2*np+1][1], o[2*np+1][2], o[2*np+1][3],
                         c0, c1, c2, c3, b2, b3);
                ldsm4(b0, b1, b2, b3, vl_b + off);
                mma16816(o[2*np][0], o[2*np][1], o[2*np][2], o[2*np][3],
                         a0, a1, a2, a3, b0, b1);
                mma16816(o[2*np+1][0], o[2*np+1][1], o[2*np+1][2], o[2*np+1][3],
                         a0, a1, a2, a3, b2, b3);
            }
        }
    }

    // ---- reduce l over the 4 lanes per row; store unnormalized partials ----
    lth0 += __shfl_xor_sync(0xffffffffu, lth0, 1);
    lth0 += __shfl_xor_sync(0xffffffffu, lth0, 2);
    lth1 += __shfl_xor_sync(0xffffffffu, lth1, 1);
    lth1 += __shfl_xor_sync(0xffffffffu, lth1, 2);

    const size_t row0 = (size_t)b * NT + r0g;
    const size_t row1 = (size_t)b * NT + r1g;
    float* p0 = g_po[sp] + row0 * NH;
    float* p1 = g_po[sp] + row1 * NH;
#pragma unroll
    for (int j = 0; j < 8; j++) {
        int col = 8 * j + 2 * l4;
        *(float2*)&p0[col] = make_float2(o[j][0], o[j][1]);
        *(float2*)&p1[col] = make_float2(o[j][2], o[j][3]);
    }
    if (l4 == 0) {
        g_pl[sp][row0] = lth0;
        g_pl[sp][row1] = lth1;
    }
}

// ---------------------------------------------------------------------------
// Kernel 4: combine the 2 split partials.  out = (o0+o1)/(l0+l1).
// ---------------------------------------------------------------------------
__global__ __launch_bounds__(256) void combine_kernel(float* __restrict__ out)
{
    size_t i = (size_t)blockIdx.x * 256 + threadIdx.x;
    size_t e = i * 4;
    size_t row = e >> 6;
    float inv = 1.0f / (g_pl[0][row] + g_pl[1][row]);
    float4 a = *(const float4*)&g_po[0][e];
    float4 c = *(const float4*)&g_po[1][e];
    float4 o = make_float4((a.x + c.x) * inv, (a.y + c.y) * inv,
                           (a.z + c.z) * inv, (a.w + c.w) * inv);
    *(float4*)&out[e] = o;
}

// ---------------------------------------------------------------------------
extern "C" void kernel_launch(void* const* d_in, const int* in_sizes, int n_in,
                              void* d_out, int out_size)
{
    const float* x  = (const float*)d_in[0];
    const float* Wk = (const float*)d_in[1];
    const float* Wq = (const float*)d_in[2];
    const float* Wv = (const float*)d_in[3];
    float* out = (float*)d_out;

    cudaFuncSetAttribute(attn_kernel,
                         cudaFuncAttributeMaxDynamicSharedMemorySize, SMEM_B);

    proj_kernel<<<dim3(256, 3), 256>>>(x, Wk, Wq, Wv);
    conv_qk_kernel<<<1024, 256>>>();
    conv_vt_kernel<<<dim3(64, NB), 256>>>();
    attn_kernel<<<dim3(128, NB), 128, SMEM_B>>>();
    combine_kernel<<<1024, 256>>>(out);
}

// round 11
// speedup vs baseline: 3.2985x; 1.3950x over previous
#include <cuda_runtime.h>
#include <cuda_bf16.h>
#include <cuda_fp16.h>
#include <math.h>
#include <stdint.h>

#define NB 4
#define NT 4096
#define NC 512
#define NH 64
#define NM (NB*NT)            // 16384 rows

// v fp32 (for transpose), fp16 operands, split-KV partials
__device__ float g_v[(size_t)NM * NH];
__device__ __half g_qh[(size_t)NM * NH], g_kh[(size_t)NM * NH];
__device__ __half g_vt[(size_t)NM * NH];          // [b][h][s]
__device__ float g_po[2][(size_t)NM * NH];
__device__ float g_pl[2][NM];

// ============================ helpers ======================================
__device__ __forceinline__ uint32_t smem_u32(const void* p) {
    uint32_t a;
    asm("{ .reg .u64 t; cvta.to.shared.u64 t, %1; cvt.u32.u64 %0, t; }"
        : "=r"(a) : "l"(p));
    return a;
}

__device__ __forceinline__ void ldsm4(uint32_t& r0, uint32_t& r1,
                                      uint32_t& r2, uint32_t& r3, uint32_t a) {
    asm volatile("ldmatrix.sync.aligned.m8n8.x4.shared.b16 {%0,%1,%2,%3}, [%4];"
        : "=r"(r0), "=r"(r1), "=r"(r2), "=r"(r3) : "r"(a));
}

__device__ __forceinline__ void mma16816(float& c0, float& c1, float& c2, float& c3,
                                         uint32_t a0, uint32_t a1, uint32_t a2, uint32_t a3,
                                         uint32_t b0, uint32_t b1) {
    asm volatile("mma.sync.aligned.m16n8k16.row.col.f32.f16.f16.f32 "
        "{%0,%1,%2,%3}, {%4,%5,%6,%7}, {%8,%9}, {%0,%1,%2,%3};"
        : "+f"(c0), "+f"(c1), "+f"(c2), "+f"(c3)
        : "r"(a0), "r"(a1), "r"(a2), "r"(a3), "r"(b0), "r"(b1));
}

// pack two floats -> fp16x2 (a in low half), round-to-nearest
__device__ __forceinline__ uint32_t cvt_h2(float a, float b) {
    __half2 h = __float22half2_rn(make_float2(a, b));
    return *reinterpret_cast<uint32_t*>(&h);
}

#define CP16(dst, src) \
    asm volatile("cp.async.cg.shared.global [%0], [%1], 16;" \
        :: "r"(dst), "l"(src) : "memory")
#define CP_COMMIT() asm volatile("cp.async.commit_group;" ::: "memory")
#define CP_WAIT0()  asm volatile("cp.async.wait_group 0;" ::: "memory")

// ---------------------------------------------------------------------------
// Kernel 1: fused QKV projection.  q/k written directly as fp16 (q scaled);
// v written fp32 for the transpose kernel.
// ---------------------------------------------------------------------------
__global__ __launch_bounds__(256) void proj_kernel(
    const float* __restrict__ x,
    const float* __restrict__ Wk,
    const float* __restrict__ Wq,
    const float* __restrict__ Wv)
{
    __shared__ float As[64 * 32];
    __shared__ float Bs[32 * 64];

    const int tid = threadIdx.x;
    const int ty  = tid >> 4;
    const int tx  = tid & 15;
    const int m0  = blockIdx.x * 64;
    const int w   = blockIdx.y;
    const float* __restrict__ W = (w == 0) ? Wk : (w == 1) ? Wq : Wv;

    float acc[4][4];
#pragma unroll
    for (int i = 0; i < 4; i++)
#pragma unroll
        for (int j = 0; j < 4; j++) acc[i][j] = 0.f;

    for (int k0 = 0; k0 < NC; k0 += 32) {
#pragma unroll
        for (int u = 0; u < 2; u++) {
            int f = tid + u * 256;
            int r = f >> 3, c = f & 7;
            *(float4*)&As[r * 32 + c * 4] =
                *(const float4*)&x[(size_t)(m0 + r) * NC + k0 + c * 4];
        }
#pragma unroll
        for (int u = 0; u < 2; u++) {
            int f = tid + u * 256;
            int r = f >> 4, c = f & 15;
            *(float4*)&Bs[r * 64 + c * 4] =
                *(const float4*)&W[(size_t)(k0 + r) * NH + c * 4];
        }
        __syncthreads();

#pragma unroll
        for (int kk = 0; kk < 32; kk += 4) {
            float av[4][4], bv[4][4];
#pragma unroll
            for (int i = 0; i < 4; i++) {
                float4 t4 = *(float4*)&As[(ty * 4 + i) * 32 + kk];
                av[i][0] = t4.x; av[i][1] = t4.y; av[i][2] = t4.z; av[i][3] = t4.w;
            }
#pragma unroll
            for (int t = 0; t < 4; t++) {
                float4 t4 = *(float4*)&Bs[(kk + t) * 64 + tx * 4];
                bv[t][0] = t4.x; bv[t][1] = t4.y; bv[t][2] = t4.z; bv[t][3] = t4.w;
            }
#pragma unroll
            for (int i = 0; i < 4; i++)
#pragma unroll
                for (int j = 0; j < 4; j++)
#pragma unroll
                    for (int t = 0; t < 4; t++)
                        acc[i][j] = fmaf(av[i][t], bv[t][j], acc[i][j]);
        }
        __syncthreads();
    }

    if (w == 2) {
#pragma unroll
        for (int i = 0; i < 4; i++) {
            float4 o4 = make_float4(acc[i][0], acc[i][1], acc[i][2], acc[i][3]);
            *(float4*)&g_v[(size_t)(m0 + ty * 4 + i) * NH + tx * 4] = o4;
        }
    } else {
        const float scale = (w == 1) ? 0.044194173824159216f : 1.0f;
        __half* __restrict__ outb = (w == 0) ? g_kh : g_qh;
#pragma unroll
        for (int i = 0; i < 4; i++) {
            uint2 r2;
            r2.x = cvt_h2(acc[i][0] * scale, acc[i][1] * scale);
            r2.y = cvt_h2(acc[i][2] * scale, acc[i][3] * scale);
            *(uint2*)&outb[(size_t)(m0 + ty * 4 + i) * NH + tx * 4] = r2;
        }
    }
}

// ---------------------------------------------------------------------------
// Kernel 2: v fp32 [b][s][h] -> vt fp16 [b][h][s]  (tiled transpose)
// ---------------------------------------------------------------------------
__global__ __launch_bounds__(256) void conv_vt_kernel()
{
    __shared__ float t[64][65];
    const int b  = blockIdx.y;
    const int st = blockIdx.x;
    const int tid = threadIdx.x;

    const float* vp = g_v + ((size_t)b * NT + (size_t)st * 64) * NH;
#pragma unroll
    for (int u = 0; u < 4; u++) {
        int f = tid + u * 256;
        int r = f >> 4, c4 = f & 15;
        float4 v4 = *(const float4*)&vp[(size_t)r * NH + c4 * 4];
        t[r][c4 * 4 + 0] = v4.x; t[r][c4 * 4 + 1] = v4.y;
        t[r][c4 * 4 + 2] = v4.z; t[r][c4 * 4 + 3] = v4.w;
    }
    __syncthreads();

#pragma unroll
    for (int u = 0; u < 4; u++) {
        int f = tid + u * 256;
        int h = f >> 4, c4 = f & 15;
        uint2 p;
        p.x = cvt_h2(t[c4 * 4 + 0][h], t[c4 * 4 + 1][h]);
        p.y = cvt_h2(t[c4 * 4 + 2][h], t[c4 * 4 + 3][h]);
        size_t e = ((size_t)b * NH + h) * NT + (size_t)st * 64 + c4 * 4;
        *(uint2*)&g_vt[e] = p;
    }
}

// ---------------------------------------------------------------------------
// Kernel 3: FA2-style attention on fp16 mma.sync, split-KV x2, cp.async
// double-buffered.  Single fp16 QK product; single fp16 PV product;
// l accumulated from the ROUNDED fp16 p values (consistent normalization).
// ---------------------------------------------------------------------------
#define KSTR 72
#define TILE_B (64 * KSTR * 2)      // 9216 B per array
#define BUF_B  (2 * TILE_B)         // 18432 B: {Kh, Vt}
#define SMEM_B (2 * BUF_B)          // 36864 B

__device__ __forceinline__ void fill_tile(uint32_t dstb, int b, int kt, int tid)
{
    const char* khp = (const char*)(g_kh + ((size_t)b * NT + (size_t)kt * 64) * NH);
    const char* vtp = (const char*)(g_vt + (size_t)b * NH * NT + (size_t)kt * 64);
#pragma unroll
    for (int u = 0; u < 4; u++) {
        int f = tid + u * 128;
        int r = f >> 3, c = f & 7;
        uint32_t so = (uint32_t)(r * KSTR) * 2 + c * 16;
        CP16(dstb + so,          khp + (size_t)r * 128 + c * 16);
        CP16(dstb + TILE_B + so, vtp + (size_t)r * (NT * 2) + c * 16);
    }
}

__global__ __launch_bounds__(128, 3) void attn_kernel()
{
    extern __shared__ char smc[];
    const uint32_t smb = smem_u32(smc);

    const int tid  = threadIdx.x;
    const int w    = tid >> 5;
    const int lane = tid & 31;
    const int g    = lane >> 2;
    const int l4   = lane & 3;
    const int qt   = 63 - (blockIdx.x >> 1);   // LPT
    const int sp   = blockIdx.x & 1;
    const int b    = blockIdx.y;
    const int lo   = sp * (qt + 1) / 2;
    const int hi   = (sp + 1) * (qt + 1) / 2;
    const int nu   = hi - lo;

    // ldmatrix lane->addr offsets (elements)
    const int rowA = lane & 15;
    const int kofA = (lane & 16) >> 1;
    const int laneA = rowA * KSTR + kofA;
    const int rowB = (lane & 7) | ((lane & 16) >> 1);
    const int kofB = (lane & 8);
    const int laneB = rowB * KSTR + kofB;

    // ---- stage Q (fp16) through buf1's Kh area; capture fragments ----
    uint32_t qh[4][4];
    {
        char* qs = smc + BUF_B;
        const uint32_t qsb = smb + BUF_B;
        const char* qhp = (const char*)(g_qh + ((size_t)b * NT + (size_t)qt * 64) * NH);
#pragma unroll
        for (int u = 0; u < 4; u++) {
            int f = tid + u * 128;
            int r = f >> 3, c = f & 7;
            *(uint4*)(qs + (r * KSTR) * 2 + c * 16) = *(const uint4*)(qhp + r * 128 + c * 16);
        }
        __syncthreads();
#pragma unroll
        for (int kc = 0; kc < 4; kc++)
            ldsm4(qh[kc][0], qh[kc][1], qh[kc][2], qh[kc][3],
                  qsb + (uint32_t)(w * 16 * KSTR + kc * 16 + laneA) * 2);
        __syncthreads();
    }

    float o[8][4];
#pragma unroll
    for (int j = 0; j < 8; j++)
#pragma unroll
        for (int c = 0; c < 4; c++) o[j][c] = 0.f;
    float lth0 = 0.f, lth1 = 0.f;

    const int r0g = qt * 64 + w * 16 + g;
    const int r1g = r0g + 8;

    if (nu > 0) { fill_tile(smb, b, lo, tid); CP_COMMIT(); }

    for (int u = 0; u < nu; u++) {
        const int kt = lo + u;
        const uint32_t bcur = smb + (u & 1) * BUF_B;
        const uint32_t kh_b = bcur;
        const uint32_t vt_b = bcur + TILE_B;

        CP_WAIT0();
        __syncthreads();                       // tile u ready; prior reads done
        if (u + 1 < nu) {
            fill_tile(smb + ((u + 1) & 1) * BUF_B, b, kt + 1, tid);
            CP_COMMIT();
        }

        // ---- S = Q * K^T (single fp16 product) ----
        float s[8][4];
#pragma unroll
        for (int j = 0; j < 8; j++)
#pragma unroll
            for (int c = 0; c < 4; c++) s[j][c] = 0.f;

#pragma unroll
        for (int jp = 0; jp < 4; jp++) {
#pragma unroll
            for (int kc = 0; kc < 4; kc++) {
                uint32_t off = (uint32_t)(jp * 16 * KSTR + kc * 16 + laneB) * 2;
                uint32_t b0, b1, b2, b3;
                ldsm4(b0, b1, b2, b3, kh_b + off);
                mma16816(s[2*jp][0], s[2*jp][1], s[2*jp][2], s[2*jp][3],
                         qh[kc][0], qh[kc][1], qh[kc][2], qh[kc][3], b0, b1);
                mma16816(s[2*jp+1][0], s[2*jp+1][1], s[2*jp+1][2], s[2*jp+1][3],
                         qh[kc][0], qh[kc][1], qh[kc][2], qh[kc][3], b2, b3);
            }
        }

        // ---- exp + causal mask; pack rounded P (fp16); l from ROUNDED p ----
        uint32_t paH[8][2];
#pragma unroll
        for (int j = 0; j < 8; j++) {
            int cb = kt * 64 + 8 * j + 2 * l4;
            float p00 = (cb     <= r0g) ? __expf(s[j][0]) : 0.f;
            float p01 = (cb + 1 <= r0g) ? __expf(s[j][1]) : 0.f;
            float p10 = (cb     <= r1g) ? __expf(s[j][2]) : 0.f;
            float p11 = (cb + 1 <= r1g) ? __expf(s[j][3]) : 0.f;
            uint32_t h0 = cvt_h2(p00, p01);
            uint32_t h1 = cvt_h2(p10, p11);
            paH[j][0] = h0;
            paH[j][1] = h1;
            __half2 hh0 = *reinterpret_cast<__half2*>(&h0);
            __half2 hh1 = *reinterpret_cast<__half2*>(&h1);
            float2 f0 = __half22float2(hh0);
            float2 f1 = __half22float2(hh1);
            lth0 += f0.x + f0.y;
            lth1 += f1.x + f1.y;
        }

        // ---- O += P * V (single fp16 product) ----
#pragma unroll
        for (int np = 0; np < 4; np++) {
#pragma unroll
            for (int kc = 0; kc < 4; kc++) {
                uint32_t off = (uint32_t)(np * 16 * KSTR + kc * 16 + laneB) * 2;
                uint32_t b0, b1, b2, b3;
                ldsm4(b0, b1, b2, b3, vt_b + off);
                mma16816(o[2*np][0], o[2*np][1], o[2*np][2], o[2*np][3],
                         paH[2*kc][0], paH[2*kc][1], paH[2*kc+1][0], paH[2*kc+1][1],
                         b0, b1);
                mma16816(o[2*np+1][0], o[2*np+1][1], o[2*np+1][2], o[2*np+1][3],
                         paH[2*kc][0], paH[2*kc][1], paH[2*kc+1][0], paH[2*kc+1][1],
                         b2, b3);
            }
        }
    }

    // ---- reduce l over the 4 lanes per row; store unnormalized partials ----
    lth0 += __shfl_xor_sync(0xffffffffu, lth0, 1);
    lth0 += __shfl_xor_sync(0xffffffffu, lth0, 2);
    lth1 += __shfl_xor_sync(0xffffffffu, lth1, 1);
    lth1 += __shfl_xor_sync(0xffffffffu, lth1, 2);

    const size_t row0 = (size_t)b * NT + r0g;
    const size_t row1 = (size_t)b * NT + r1g;
    float* p0 = g_po[sp] + row0 * NH;
    float* p1 = g_po[sp] + row1 * NH;
#pragma unroll
    for (int j = 0; j < 8; j++) {
        int col = 8 * j + 2 * l4;
        *(float2*)&p0[col] = make_float2(o[j][0], o[j][1]);
        *(float2*)&p1[col] = make_float2(o[j][2], o[j][3]);
    }
    if (l4 == 0) {
        g_pl[sp][row0] = lth0;
        g_pl[sp][row1] = lth1;
    }
}

// ---------------------------------------------------------------------------
// Kernel 4: combine the 2 split partials.  out = (o0+o1)/(l0+l1).
// ---------------------------------------------------------------------------
__global__ __launch_bounds__(256) void combine_kernel(float* __restrict__ out)
{
    size_t i = (size_t)blockIdx.x * 256 + threadIdx.x;
    size_t e = i * 4;
    size_t row = e >> 6;
    float inv = 1.0f / (g_pl[0][row] + g_pl[1][row]);
    float4 a = *(const float4*)&g_po[0][e];
    float4 c = *(const float4*)&g_po[1][e];
    float4 o = make_float4((a.x + c.x) * inv, (a.y + c.y) * inv,
                           (a.z + c.z) * inv, (a.w + c.w) * inv);
    *(float4*)&out[e] = o;
}

// ---------------------------------------------------------------------------
extern "C" void kernel_launch(void* const* d_in, const int* in_sizes, int n_in,
                              void* d_out, int out_size)
{
    const float* x  = (const float*)d_in[0];
    const float* Wk = (const float*)d_in[1];
    const float* Wq = (const float*)d_in[2];
    const float* Wv = (const float*)d_in[3];
    float* out = (float*)d_out;

    cudaFuncSetAttribute(attn_kernel,
                         cudaFuncAttributeMaxDynamicSharedMemorySize, SMEM_B);

    proj_kernel<<<dim3(256, 3), 256>>>(x, Wk, Wq, Wv);
    conv_vt_kernel<<<dim3(64, NB), 256>>>();
    attn_kernel<<<dim3(128, NB), 128, SMEM_B>>>();
    combine_kernel<<<1024, 256>>>(out);
}

// round 12
// speedup vs baseline: 5.7084x; 1.7306x over previous
#include <cuda_runtime.h>
#include <cuda_fp16.h>
#include <math.h>
#include <stdint.h>

#define NB 4
#define NT 4096
#define NC 512
#define NH 64
#define NM (NB*NT)            // 16384 rows

// fp16 operands + split-KV partials
__device__ __half g_wt[192 * NC];                 // [n][k]: n 0-63=k,64-127=q(scaled),128-191=v
__device__ __half g_qh[(size_t)NM * NH], g_kh[(size_t)NM * NH];
__device__ __half g_v16[(size_t)NM * NH];         // [b][s][h]
__device__ __half g_vt[(size_t)NM * NH];          // [b][h][s]
__device__ float g_po[2][(size_t)NM * NH];
__device__ float g_pl[2][NM];

// ============================ helpers ======================================
__device__ __forceinline__ uint32_t smem_u32(const void* p) {
    uint32_t a;
    asm("{ .reg .u64 t; cvta.to.shared.u64 t, %1; cvt.u32.u64 %0, t; }"
        : "=r"(a) : "l"(p));
    return a;
}

__device__ __forceinline__ void ldsm4(uint32_t& r0, uint32_t& r1,
                                      uint32_t& r2, uint32_t& r3, uint32_t a) {
    asm volatile("ldmatrix.sync.aligned.m8n8.x4.shared.b16 {%0,%1,%2,%3}, [%4];"
        : "=r"(r0), "=r"(r1), "=r"(r2), "=r"(r3) : "r"(a));
}

__device__ __forceinline__ void mma16816(float& c0, float& c1, float& c2, float& c3,
                                         uint32_t a0, uint32_t a1, uint32_t a2, uint32_t a3,
                                         uint32_t b0, uint32_t b1) {
    asm volatile("mma.sync.aligned.m16n8k16.row.col.f32.f16.f16.f32 "
        "{%0,%1,%2,%3}, {%4,%5,%6,%7}, {%8,%9}, {%0,%1,%2,%3};"
        : "+f"(c0), "+f"(c1), "+f"(c2), "+f"(c3)
        : "r"(a0), "r"(a1), "r"(a2), "r"(a3), "r"(b0), "r"(b1));
}

__device__ __forceinline__ uint32_t cvt_h2(float a, float b) {
    __half2 h = __float22half2_rn(make_float2(a, b));
    return *reinterpret_cast<uint32_t*>(&h);
}

#define CP16(dst, src) \
    asm volatile("cp.async.cg.shared.global [%0], [%1], 16;" \
        :: "r"(dst), "l"(src) : "memory")
#define CP_COMMIT() asm volatile("cp.async.commit_group;" ::: "memory")
#define CP_WAIT0()  asm volatile("cp.async.wait_group 0;" ::: "memory")

// ---------------------------------------------------------------------------
// Kernel 0: build W^T fp16 [192][512] from Wk|Wq|Wv (fp32 [512][64]).
// 1/sqrt(C) folded into the q block.  grid (8 k-tiles, 3 matrices).
// ---------------------------------------------------------------------------
__global__ __launch_bounds__(256) void wt_prep_kernel(
    const float* __restrict__ Wk,
    const float* __restrict__ Wq,
    const float* __restrict__ Wv)
{
    __shared__ float t[64][65];
    const int k0  = blockIdx.x * 64;
    const int wsel = blockIdx.y;
    const int tid = threadIdx.x;
    const float* __restrict__ W = (wsel == 0) ? Wk : (wsel == 1) ? Wq : Wv;
    const float scale = (wsel == 1) ? 0.044194173824159216f : 1.0f;

#pragma unroll
    for (int u = 0; u < 4; u++) {
        int f = tid + u * 256;
        int r = f >> 4, c4 = f & 15;
        float4 w4 = *(const float4*)&W[(size_t)(k0 + r) * NH + c4 * 4];
        t[r][c4 * 4 + 0] = w4.x; t[r][c4 * 4 + 1] = w4.y;
        t[r][c4 * 4 + 2] = w4.z; t[r][c4 * 4 + 3] = w4.w;
    }
    __syncthreads();

#pragma unroll
    for (int u = 0; u < 4; u++) {
        int f = tid + u * 256;
        int n = f >> 4, c4 = f & 15;
        uint2 p;
        p.x = cvt_h2(t[c4 * 4 + 0][n] * scale, t[c4 * 4 + 1][n] * scale);
        p.y = cvt_h2(t[c4 * 4 + 2][n] * scale, t[c4 * 4 + 3][n] * scale);
        *(uint2*)&g_wt[(size_t)(wsel * 64 + n) * NC + k0 + c4 * 4] = p;
    }
}

// ---------------------------------------------------------------------------
// Kernel 1: QKV projection on fp16 mma.sync.
// grid (128 M-tiles, 2 N-halves); 256 thr / 8 warps; warp = 16 rows x 96 cols.
// x converted fp32->fp16 in registers (software pipeline), W^T via cp.async.
// ---------------------------------------------------------------------------
#define XSTR 40
__global__ __launch_bounds__(256, 2) void proj_kernel(const float* __restrict__ x)
{
    __shared__ __half xs[128 * XSTR];
    __shared__ __half ws[96 * XSTR];

    const int tid  = threadIdx.x;
    const int w    = tid >> 5;
    const int lane = tid & 31;
    const int g    = lane >> 2;
    const int l4   = lane & 3;
    const int m0   = blockIdx.x * 128;
    const int nbase = blockIdx.y * 96;

    const uint32_t xs_b = smem_u32(xs);
    const uint32_t ws_b = smem_u32(ws);

    const int laneA = (lane & 15) * XSTR + ((lane & 16) >> 1);
    const int laneB = ((lane & 7) | ((lane & 16) >> 1)) * XSTR + (lane & 8);

    // per-thread load roles
    const int xr = tid >> 1, xh = tid & 1;          // x: row, 16-col half
    const int wr = tid >> 1, wh = tid & 1;          // w: row (t<192 only)
    const float* xp = x + (size_t)(m0 + xr) * NC + xh * 16;
    const __half* wp = g_wt + (size_t)(nbase + wr) * NC + wh * 16;

    float c[12][4];
#pragma unroll
    for (int j = 0; j < 12; j++)
#pragma unroll
        for (int q = 0; q < 4; q++) c[j][q] = 0.f;

    // prefetch step 0
    float4 xr4[4];
    uint4 wr4[2];
#pragma unroll
    for (int q = 0; q < 4; q++) xr4[q] = *(const float4*)(xp + q * 4);
    if (tid < 192) {
        wr4[0] = *(const uint4*)(wp);
        wr4[1] = *(const uint4*)(wp + 8);
    }

    for (int s = 0; s < 16; s++) {
        __syncthreads();   // previous step's ldmatrix reads complete
        // store staged chunk
        {
            uint32_t px[8];
#pragma unroll
            for (int q = 0; q < 4; q++) {
                px[q * 2 + 0] = cvt_h2(xr4[q].x, xr4[q].y);
                px[q * 2 + 1] = cvt_h2(xr4[q].z, xr4[q].w);
            }
            uint4* d = (uint4*)&xs[xr * XSTR + xh * 16];
            d[0] = make_uint4(px[0], px[1], px[2], px[3]);
            d[1] = make_uint4(px[4], px[5], px[6], px[7]);
            if (tid < 192) {
                uint4* dw = (uint4*)&ws[wr * XSTR + wh * 16];
                dw[0] = wr4[0];
                dw[1] = wr4[1];
            }
        }
        __syncthreads();

        // prefetch step s+1 (latency hidden under MMAs below)
        if (s < 15) {
            const float* xpn = xp + (s + 1) * 32;
#pragma unroll
            for (int q = 0; q < 4; q++) xr4[q] = *(const float4*)(xpn + q * 4);
            if (tid < 192) {
                const __half* wpn = wp + (s + 1) * 32;
                wr4[0] = *(const uint4*)(wpn);
                wr4[1] = *(const uint4*)(wpn + 8);
            }
        }

        // MMAs over this 32-deep chunk
#pragma unroll
        for (int kc = 0; kc < 2; kc++) {
            uint32_t a0, a1, a2, a3;
            ldsm4(a0, a1, a2, a3,
                  xs_b + (uint32_t)(w * 16 * XSTR + kc * 16 + laneA) * 2);
#pragma unroll
            for (int jp = 0; jp < 6; jp++) {
                uint32_t b0, b1, b2, b3;
                ldsm4(b0, b1, b2, b3,
                      ws_b + (uint32_t)(jp * 16 * XSTR + kc * 16 + laneB) * 2);
                mma16816(c[2*jp][0], c[2*jp][1], c[2*jp][2], c[2*jp][3],
                         a0, a1, a2, a3, b0, b1);
                mma16816(c[2*jp+1][0], c[2*jp+1][1], c[2*jp+1][2], c[2*jp+1][3],
                         a0, a1, a2, a3, b2, b3);
            }
        }
    }

    // epilogue: route each 8-col fragment to k / q / v fp16 arrays
    const int r0 = m0 + w * 16 + g;
    const int r1 = r0 + 8;
#pragma unroll
    for (int j = 0; j < 12; j++) {
        int col = nbase + 8 * j + 2 * l4;
        int arr = col >> 6;
        int ci  = col & 63;
        __half* dst = (arr == 0) ? g_kh : (arr == 1) ? g_qh : g_v16;
        *(uint32_t*)&dst[(size_t)r0 * NH + ci] = cvt_h2(c[j][0], c[j][1]);
        *(uint32_t*)&dst[(size_t)r1 * NH + ci] = cvt_h2(c[j][2], c[j][3]);
    }
}

// ---------------------------------------------------------------------------
// Kernel 2: v fp16 [b][s][h] -> vt fp16 [b][h][s]  (pure relayout)
// ---------------------------------------------------------------------------
__global__ __launch_bounds__(256) void conv_vt_kernel()
{
    __shared__ __half t[64][68];
    const int b  = blockIdx.y;
    const int st = blockIdx.x;
    const int tid = threadIdx.x;

    const __half* vp = g_v16 + ((size_t)b * NT + (size_t)st * 64) * NH;
#pragma unroll
    for (int u = 0; u < 4; u++) {
        int f = tid + u * 256;
        int r = f >> 4, c4 = f & 15;
        uint2 p = *(const uint2*)&vp[(size_t)r * NH + c4 * 4];
        __half2 h0 = *reinterpret_cast<__half2*>(&p.x);
        __half2 h1 = *reinterpret_cast<__half2*>(&p.y);
        t[r][c4 * 4 + 0] = __low2half(h0);  t[r][c4 * 4 + 1] = __high2half(h0);
        t[r][c4 * 4 + 2] = __low2half(h1);  t[r][c4 * 4 + 3] = __high2half(h1);
    }
    __syncthreads();

#pragma unroll
    for (int u = 0; u < 4; u++) {
        int f = tid + u * 256;
        int h = f >> 4, c4 = f & 15;
        __half2 h0 = __halves2half2(t[c4 * 4 + 0][h], t[c4 * 4 + 1][h]);
        __half2 h1 = __halves2half2(t[c4 * 4 + 2][h], t[c4 * 4 + 3][h]);
        uint2 p;
        p.x = *reinterpret_cast<uint32_t*>(&h0);
        p.y = *reinterpret_cast<uint32_t*>(&h1);
        *(uint2*)&g_vt[((size_t)b * NH + h) * NT + (size_t)st * 64 + c4 * 4] = p;
    }
}

// ---------------------------------------------------------------------------
// Kernel 3: FA2-style attention on fp16 mma.sync, split-KV x2, cp.async
// double-buffered (unchanged from R11-passing version).
// ---------------------------------------------------------------------------
#define KSTR 72
#define TILE_B (64 * KSTR * 2)      // 9216 B per array
#define BUF_B  (2 * TILE_B)         // 18432 B: {Kh, Vt}
#define SMEM_B (2 * BUF_B)          // 36864 B

__device__ __forceinline__ void fill_tile(uint32_t dstb, int b, int kt, int tid)
{
    const char* khp = (const char*)(g_kh + ((size_t)b * NT + (size_t)kt * 64) * NH);
    const char* vtp = (const char*)(g_vt + (size_t)b * NH * NT + (size_t)kt * 64);
#pragma unroll
    for (int u = 0; u < 4; u++) {
        int f = tid + u * 128;
        int r = f >> 3, c = f & 7;
        uint32_t so = (uint32_t)(r * KSTR) * 2 + c * 16;
        CP16(dstb + so,          khp + (size_t)r * 128 + c * 16);
        CP16(dstb + TILE_B + so, vtp + (size_t)r * (NT * 2) + c * 16);
    }
}

__global__ __launch_bounds__(128, 3) void attn_kernel()
{
    extern __shared__ char smc[];
    const uint32_t smb = smem_u32(smc);

    const int tid  = threadIdx.x;
    const int w    = tid >> 5;
    const int lane = tid & 31;
    const int g    = lane >> 2;
    const int l4   = lane & 3;
    const int qt   = 63 - (blockIdx.x >> 1);   // LPT
    const int sp   = blockIdx.x & 1;
    const int b    = blockIdx.y;
    const int lo   = sp * (qt + 1) / 2;
    const int hi   = (sp + 1) * (qt + 1) / 2;
    const int nu   = hi - lo;

    const int rowA = lane & 15;
    const int kofA = (lane & 16) >> 1;
    const int laneA = rowA * KSTR + kofA;
    const int rowB = (lane & 7) | ((lane & 16) >> 1);
    const int kofB = (lane & 8);
    const int laneB = rowB * KSTR + kofB;

    // ---- stage Q (fp16) through buf1's Kh area; capture fragments ----
    uint32_t qh[4][4];
    {
        char* qs = smc + BUF_B;
        const uint32_t qsb = smb + BUF_B;
        const char* qhp = (const char*)(g_qh + ((size_t)b * NT + (size_t)qt * 64) * NH);
#pragma unroll
        for (int u = 0; u < 4; u++) {
            int f = tid + u * 128;
            int r = f >> 3, c = f & 7;
            *(uint4*)(qs + (r * KSTR) * 2 + c * 16) = *(const uint4*)(qhp + r * 128 + c * 16);
        }
        __syncthreads();
#pragma unroll
        for (int kc = 0; kc < 4; kc++)
            ldsm4(qh[kc][0], qh[kc][1], qh[kc][2], qh[kc][3],
                  qsb + (uint32_t)(w * 16 * KSTR + kc * 16 + laneA) * 2);
        __syncthreads();
    }

    float o[8][4];
#pragma unroll
    for (int j = 0; j < 8; j++)
#pragma unroll
        for (int c = 0; c < 4; c++) o[j][c] = 0.f;
    float lth0 = 0.f, lth1 = 0.f;

    const int r0g = qt * 64 + w * 16 + g;
    const int r1g = r0g + 8;

    if (nu > 0) { fill_tile(smb, b, lo, tid); CP_COMMIT(); }

    for (int u = 0; u < nu; u++) {
        const int kt = lo + u;
        const uint32_t bcur = smb + (u & 1) * BUF_B;
        const uint32_t kh_b = bcur;
        const uint32_t vt_b = bcur + TILE_B;

        CP_WAIT0();
        __syncthreads();
        if (u + 1 < nu) {
            fill_tile(smb + ((u + 1) & 1) * BUF_B, b, kt + 1, tid);
            CP_COMMIT();
        }

        // ---- S = Q * K^T ----
        float s[8][4];
#pragma unroll
        for (int j = 0; j < 8; j++)
#pragma unroll
            for (int c = 0; c < 4; c++) s[j][c] = 0.f;

#pragma unroll
        for (int jp = 0; jp < 4; jp++) {
#pragma unroll
            for (int kc = 0; kc < 4; kc++) {
                uint32_t off = (uint32_t)(jp * 16 * KSTR + kc * 16 + laneB) * 2;
                uint32_t b0, b1, b2, b3;
                ldsm4(b0, b1, b2, b3, kh_b + off);
                mma16816(s[2*jp][0], s[2*jp][1], s[2*jp][2], s[2*jp][3],
                         qh[kc][0], qh[kc][1], qh[kc][2], qh[kc][3], b0, b1);
                mma16816(s[2*jp+1][0], s[2*jp+1][1], s[2*jp+1][2], s[2*jp+1][3],
                         qh[kc][0], qh[kc][1], qh[kc][2], qh[kc][3], b2, b3);
            }
        }

        // ---- exp + causal mask; pack rounded P; l from ROUNDED p ----
        uint32_t paH[8][2];
#pragma unroll
        for (int j = 0; j < 8; j++) {
            int cb = kt * 64 + 8 * j + 2 * l4;
            float p00 = (cb     <= r0g) ? __expf(s[j][0]) : 0.f;
            float p01 = (cb + 1 <= r0g) ? __expf(s[j][1]) : 0.f;
            float p10 = (cb     <= r1g) ? __expf(s[j][2]) : 0.f;
            float p11 = (cb + 1 <= r1g) ? __expf(s[j][3]) : 0.f;
            uint32_t h0 = cvt_h2(p00, p01);
            uint32_t h1 = cvt_h2(p10, p11);
            paH[j][0] = h0;
            paH[j][1] = h1;
            __half2 hh0 = *reinterpret_cast<__half2*>(&h0);
            __half2 hh1 = *reinterpret_cast<__half2*>(&h1);
            float2 f0 = __half22float2(hh0);
            float2 f1 = __half22float2(hh1);
            lth0 += f0.x + f0.y;
            lth1 += f1.x + f1.y;
        }

        // ---- O += P * V ----
#pragma unroll
        for (int np = 0; np < 4; np++) {
#pragma unroll
            for (int kc = 0; kc < 4; kc++) {
                uint32_t off = (uint32_t)(np * 16 * KSTR + kc * 16 + laneB) * 2;
                uint32_t b0, b1, b2, b3;
                ldsm4(b0, b1, b2, b3, vt_b + off);
                mma16816(o[2*np][0], o[2*np][1], o[2*np][2], o[2*np][3],
                         paH[2*kc][0], paH[2*kc][1], paH[2*kc+1][0], paH[2*kc+1][1],
                         b0, b1);
                mma16816(o[2*np+1][0], o[2*np+1][1], o[2*np+1][2], o[2*np+1][3],
                         paH[2*kc][0], paH[2*kc][1], paH[2*kc+1][0], paH[2*kc+1][1],
                         b2, b3);
            }
        }
    }

    // ---- reduce l; store unnormalized partials ----
    lth0 += __shfl_xor_sync(0xffffffffu, lth0, 1);
    lth0 += __shfl_xor_sync(0xffffffffu, lth0, 2);
    lth1 += __shfl_xor_sync(0xffffffffu, lth1, 1);
    lth1 += __shfl_xor_sync(0xffffffffu, lth1, 2);

    const size_t row0 = (size_t)b * NT + r0g;
    const size_t row1 = (size_t)b * NT + r1g;
    float* p0 = g_po[sp] + row0 * NH;
    float* p1 = g_po[sp] + row1 * NH;
#pragma unroll
    for (int j = 0; j < 8; j++) {
        int col = 8 * j + 2 * l4;
        *(float2*)&p0[col] = make_float2(o[j][0], o[j][1]);
        *(float2*)&p1[col] = make_float2(o[j][2], o[j][3]);
    }
    if (l4 == 0) {
        g_pl[sp][row0] = lth0;
        g_pl[sp][row1] = lth1;
    }
}

// ---------------------------------------------------------------------------
// Kernel 4: combine the 2 split partials.  out = (o0+o1)/(l0+l1).
// ---------------------------------------------------------------------------
__global__ __launch_bounds__(256) void combine_kernel(float* __restrict__ out)
{
    size_t i = (size_t)blockIdx.x * 256 + threadIdx.x;
    size_t e = i * 4;
    size_t row = e >> 6;
    float inv = 1.0f / (g_pl[0][row] + g_pl[1][row]);
    float4 a = *(const float4*)&g_po[0][e];
    float4 c = *(const float4*)&g_po[1][e];
    float4 o = make_float4((a.x + c.x) * inv, (a.y + c.y) * inv,
                           (a.z + c.z) * inv, (a.w + c.w) * inv);
    *(float4*)&out[e] = o;
}

// ---------------------------------------------------------------------------
extern "C" void kernel_launch(void* const* d_in, const int* in_sizes, int n_in,
                              void* d_out, int out_size)
{
    const float* x  = (const float*)d_in[0];
    const float* Wk = (const float*)d_in[1];
    const float* Wq = (const float*)d_in[2];
    const float* Wv = (const float*)d_in[3];
    float* out = (float*)d_out;

    cudaFuncSetAttribute(attn_kernel,
                         cudaFuncAttributeMaxDynamicSharedMemorySize, SMEM_B);

    wt_prep_kernel<<<dim3(8, 3), 256>>>(Wk, Wq, Wv);
    proj_kernel<<<dim3(128, 2), 256>>>(x);
    conv_vt_kernel<<<dim3(64, NB), 256>>>();
    attn_kernel<<<dim3(128, NB), 128, SMEM_B>>>();
    combine_kernel<<<1024, 256>>>(out);
}